// round 10
// baseline (speedup 1.0000x reference)
#include <cuda_runtime.h>
#include <cuda_bf16.h>
#include <cstdint>

// Problem constants
#define BB 2
#define TT 2048
#define CC 1024
#define HH 16
#define DD 64

// Scratch (allocation-free rule: __device__ globals)
__device__ float g_Q[BB * HH * TT * DD];   // [B,H,T,D]
__device__ float g_K[BB * HH * TT * DD];
__device__ float g_V[BB * HH * TT * DD];
__device__ float g_Y[BB * TT * CC];        // attention output, [B,T,C]

__device__ __forceinline__ void mma_bf16(float (&c)[4], const uint32_t (&a)[4],
                                         const uint32_t (&b)[2]) {
    asm volatile(
        "mma.sync.aligned.m16n8k16.row.col.f32.bf16.bf16.f32 "
        "{%0,%1,%2,%3}, {%4,%5,%6,%7}, {%8,%9}, {%0,%1,%2,%3};"
        : "+f"(c[0]), "+f"(c[1]), "+f"(c[2]), "+f"(c[3])
        : "r"(a[0]), "r"(a[1]), "r"(a[2]), "r"(a[3]), "r"(b[0]), "r"(b[1]));
}

__device__ __forceinline__ void mma_tf32(float (&c)[4], const uint32_t (&a)[4],
                                         const uint32_t (&b)[2]) {
    asm volatile(
        "mma.sync.aligned.m16n8k8.row.col.f32.tf32.tf32.f32 "
        "{%0,%1,%2,%3}, {%4,%5,%6,%7}, {%8,%9}, {%0,%1,%2,%3};"
        : "+f"(c[0]), "+f"(c[1]), "+f"(c[2]), "+f"(c[3])
        : "r"(a[0]), "r"(a[1]), "r"(a[2]), "r"(a[3]), "r"(b[0]), "r"(b[1]));
}

__device__ __forceinline__ float to_tf32(float x) {
    float r;
    asm("cvt.rna.tf32.f32 %0, %1;" : "=f"(r) : "f"(x));
    return r;
}

// split x into bf16 hi + bf16 lo (packed pairs along k) — attention PV only
__device__ __forceinline__ void split2(float x0, float x1, uint32_t& hi, uint32_t& lo) {
    __nv_bfloat16 h0 = __float2bfloat16_rn(x0);
    __nv_bfloat16 h1 = __float2bfloat16_rn(x1);
    __nv_bfloat16 l0 = __float2bfloat16_rn(x0 - __bfloat162float(h0));
    __nv_bfloat16 l1 = __float2bfloat16_rn(x1 - __bfloat162float(h1));
    hi = (uint32_t)__bfloat16_as_ushort(h1) << 16 | __bfloat16_as_ushort(h0);
    lo = (uint32_t)__bfloat16_as_ushort(l1) << 16 | __bfloat16_as_ushort(l0);
}

// ---------------------------------------------------------------------------
// tf32 mma.sync GEMM: double-buffered smem (one sync/k-tile) AND 2 CTAs/SM.
// CTA 128x128, BK=32, 8 warps (2 M x 4 N), warp tile 64x32, m16n8k8.
// MODE 0: A = x (arg), scatter to g_Q/g_K/g_V; MODE 1: A = g_Y symbol -> out
// ---------------------------------------------------------------------------
#define GM_BM 128
#define GM_BN 128
#define GM_BK 32
#define GM_LDS 36
#define GM_NKT (CC / GM_BK)  // 32
#define GM_ASZ (GM_BM * GM_LDS)
#define GM_BSZ (GM_BN * GM_LDS)
#define GM_SMEM_BYTES (4 * 2 * (GM_ASZ + GM_BSZ))   // 73728 -> 2 CTAs = 147KB

template <int NN, int MODE>
__global__ __launch_bounds__(256, 2) void gemm_mma_kernel(
    const float* __restrict__ Ain, const float* __restrict__ W,
    const float* __restrict__ bias, float* __restrict__ out) {
    extern __shared__ uint32_t dsm[];
    uint32_t* Asb = dsm;                     // [2][GM_ASZ]
    uint32_t* Bsb = dsm + 2 * GM_ASZ;        // [2][GM_BSZ]

    const float* __restrict__ A = (MODE == 1) ? (const float*)g_Y : Ain;

    const int tid = threadIdx.x;
    const int lane = tid & 31;
    const int warp = tid >> 5;
    const int wm = warp & 1;
    const int wn = warp >> 1;
    const int g = lane >> 2;
    const int t = lane & 3;
    const int m0 = blockIdx.y * GM_BM;
    const int n0 = blockIdx.x * GM_BN;

    const int nB = tid & 127;
    const int khB = tid >> 7;

    float4 ar[4];
    float brg[4][4];

    // --- LDG tile 0 ---
    #pragma unroll
    for (int i = 0; i < 4; i++) {
        int idx = tid + i * 256;
        ar[i] = *(const float4*)(A + (size_t)(m0 + (idx >> 3)) * CC + ((idx & 7) << 2));
        const float* wp = W + (size_t)(khB * 16 + i * 4) * NN + n0 + nB;
        brg[i][0] = wp[0];
        brg[i][1] = wp[NN];
        brg[i][2] = wp[2 * NN];
        brg[i][3] = wp[3 * NN];
    }

    // --- STS tile 0 -> buffer 0 ---
    #pragma unroll
    for (int i = 0; i < 4; i++) {
        int idx = tid + i * 256;
        int am = idx >> 3, akq = (idx & 7) << 2;
        uint4 u;
        u.x = __float_as_uint(to_tf32(ar[i].x));
        u.y = __float_as_uint(to_tf32(ar[i].y));
        u.z = __float_as_uint(to_tf32(ar[i].z));
        u.w = __float_as_uint(to_tf32(ar[i].w));
        *(uint4*)&Asb[am * GM_LDS + akq] = u;
        uint4 w;
        w.x = __float_as_uint(to_tf32(brg[i][0]));
        w.y = __float_as_uint(to_tf32(brg[i][1]));
        w.z = __float_as_uint(to_tf32(brg[i][2]));
        w.w = __float_as_uint(to_tf32(brg[i][3]));
        *(uint4*)&Bsb[nB * GM_LDS + khB * 16 + i * 4] = w;
    }
    __syncthreads();

    float acc[4][4][4] = {};

    #pragma unroll 1
    for (int kt = 0; kt < GM_NKT; kt++) {
        // --- LDG tile kt+1 into registers ---
        if (kt + 1 < GM_NKT) {
            const int k0 = (kt + 1) * GM_BK;
            #pragma unroll
            for (int i = 0; i < 4; i++) {
                int idx = tid + i * 256;
                ar[i] = *(const float4*)(A + (size_t)(m0 + (idx >> 3)) * CC + k0 + ((idx & 7) << 2));
                const float* wp = W + (size_t)(k0 + khB * 16 + i * 4) * NN + n0 + nB;
                brg[i][0] = wp[0];
                brg[i][1] = wp[NN];
                brg[i][2] = wp[2 * NN];
                brg[i][3] = wp[3 * NN];
            }
        }

        // --- compute on buffer kt&1 ---
        const uint32_t* As = Asb + (kt & 1) * GM_ASZ;
        const uint32_t* Bs = Bsb + (kt & 1) * GM_BSZ;
        #pragma unroll
        for (int ks = 0; ks < 4; ks++) {
            const int kb = ks * 8 + t;
            uint32_t af[4][4], bf[4][2];
            #pragma unroll
            for (int mf = 0; mf < 4; mf++) {
                int m = wm * 64 + mf * 16 + g;
                af[mf][0] = As[m * GM_LDS + kb];
                af[mf][1] = As[(m + 8) * GM_LDS + kb];
                af[mf][2] = As[m * GM_LDS + kb + 4];
                af[mf][3] = As[(m + 8) * GM_LDS + kb + 4];
            }
            #pragma unroll
            for (int nf = 0; nf < 4; nf++) {
                int n = wn * 32 + nf * 8 + g;
                bf[nf][0] = Bs[n * GM_LDS + kb];
                bf[nf][1] = Bs[n * GM_LDS + kb + 4];
            }
            #pragma unroll
            for (int mf = 0; mf < 4; mf++)
                #pragma unroll
                for (int nf = 0; nf < 4; nf++)
                    mma_tf32(acc[mf][nf], af[mf], bf[nf]);
        }

        // --- STS tile kt+1 -> buffer (kt+1)&1, single sync ---
        if (kt + 1 < GM_NKT) {
            uint32_t* Asn = Asb + ((kt + 1) & 1) * GM_ASZ;
            uint32_t* Bsn = Bsb + ((kt + 1) & 1) * GM_BSZ;
            #pragma unroll
            for (int i = 0; i < 4; i++) {
                int idx = tid + i * 256;
                int am = idx >> 3, akq = (idx & 7) << 2;
                uint4 u;
                u.x = __float_as_uint(to_tf32(ar[i].x));
                u.y = __float_as_uint(to_tf32(ar[i].y));
                u.z = __float_as_uint(to_tf32(ar[i].z));
                u.w = __float_as_uint(to_tf32(ar[i].w));
                *(uint4*)&Asn[am * GM_LDS + akq] = u;
                uint4 w;
                w.x = __float_as_uint(to_tf32(brg[i][0]));
                w.y = __float_as_uint(to_tf32(brg[i][1]));
                w.z = __float_as_uint(to_tf32(brg[i][2]));
                w.w = __float_as_uint(to_tf32(brg[i][3]));
                *(uint4*)&Bsn[nB * GM_LDS + khB * 16 + i * 4] = w;
            }
            __syncthreads();
        }
    }

    // --- Epilogue: bias + store straight from registers ---
    #pragma unroll
    for (int mf = 0; mf < 4; mf++) {
        #pragma unroll
        for (int half = 0; half < 2; half++) {
            int row = m0 + wm * 64 + mf * 16 + g + half * 8;
            #pragma unroll
            for (int nf = 0; nf < 4; nf++) {
                int col = n0 + wn * 32 + nf * 8 + 2 * t;
                float2 v;
                v.x = acc[mf][nf][2 * half + 0] + bias[col];
                v.y = acc[mf][nf][2 * half + 1] + bias[col + 1];
                if (MODE == 0) {
                    int which = col / CC;
                    int c2 = col % CC;
                    int h = c2 / DD, d = c2 % DD;
                    int b = row / TT, tt = row % TT;
                    float* base = (which == 0) ? g_Q : (which == 1) ? g_K : g_V;
                    *(float2*)(base + (((size_t)(b * HH + h) * TT + tt) * DD + d)) = v;
                } else {
                    *(float2*)(out + (size_t)row * NN + col) = v;
                }
            }
        }
    }
}

// ---------------------------------------------------------------------------
// Tensor-core flash attention: tf32 QK^T + bf16x3 PV (unchanged from R9)
// CTA: 128 threads / 4 warps / 64 q-rows, key tiles of 64, longest-first.
// ---------------------------------------------------------------------------
#define AK_LDS 72   // uint16 stride for V (frag bank = 4g+t, conflict-free)
#define KT_LDS 76   // uint32 stride for K (frag bank = (12g+t)%32, bijective)

__global__ __launch_bounds__(128) void attn_mma_kernel() {
    __shared__ __align__(16) uint32_t Kt[64 * KT_LDS];   // [key][d] tf32
    __shared__ __align__(16) uint16_t Vsh[64 * AK_LDS];  // transposed: [d][key]
    __shared__ __align__(16) uint16_t Vsl[64 * AK_LDS];

    const int bh = blockIdx.y;
    const int bx = gridDim.x - 1 - blockIdx.x;   // longest rows first
    const int qm0 = bx * 64;
    const int tid = threadIdx.x;
    const int lane = tid & 31;
    const int warp = tid >> 5;                   // 0..3
    const int g = lane >> 2;
    const int t = lane & 3;

    const float* Qb = g_Q + (size_t)bh * TT * DD;
    const float* Kb = g_K + (size_t)bh * TT * DD;
    const float* Vb = g_V + (size_t)bh * TT * DD;

    // --- Q as tf32 A-fragments (scale folded): 8 k8-chunks x 4 regs ---
    const int r0 = qm0 + warp * 16 + g;
    const float* q0p = Qb + (size_t)r0 * DD;
    const float* q1p = q0p + 8 * DD;
    const float sc = 0.125f;
    uint32_t Qt[8][4];
    #pragma unroll
    for (int ks = 0; ks < 8; ks++) {
        int d0 = ks * 8 + t;
        Qt[ks][0] = __float_as_uint(to_tf32(q0p[d0] * sc));
        Qt[ks][1] = __float_as_uint(to_tf32(q1p[d0] * sc));
        Qt[ks][2] = __float_as_uint(to_tf32(q0p[d0 + 4] * sc));
        Qt[ks][3] = __float_as_uint(to_tf32(q1p[d0 + 4] * sc));
    }

    float oacc[8][4] = {};
    float mrow[2] = {-1e30f, -1e30f};
    float lrow[2] = {0.f, 0.f};

    const int ntiles = bx + 1;
    const int diag = bx;   // only the last tile is masked

    #pragma unroll 1
    for (int jt = 0; jt < ntiles; jt++) {
        const int j0 = jt * 64;
        __syncthreads();
        // --- K tile [key][d] tf32; V tile transposed [d][key] bf16 hi/lo ---
        #pragma unroll
        for (int p = 0; p < 8; p++) {
            int idx = tid + p * 128;
            int key = idx >> 4;
            int d = (idx & 15) << 2;
            float4 kv = *(const float4*)(Kb + (size_t)(j0 + key) * DD + d);
            uint4 u;
            u.x = __float_as_uint(to_tf32(kv.x));
            u.y = __float_as_uint(to_tf32(kv.y));
            u.z = __float_as_uint(to_tf32(kv.z));
            u.w = __float_as_uint(to_tf32(kv.w));
            *(uint4*)&Kt[key * KT_LDS + d] = u;
            float4 vv = *(const float4*)(Vb + (size_t)(j0 + key) * DD + d);
            #pragma unroll
            for (int c = 0; c < 4; c++) {
                float f = (&vv.x)[c];
                __nv_bfloat16 fh = __float2bfloat16_rn(f);
                __nv_bfloat16 fl = __float2bfloat16_rn(f - __bfloat162float(fh));
                Vsh[(d + c) * AK_LDS + key] = __bfloat16_as_ushort(fh);
                Vsl[(d + c) * AK_LDS + key] = __bfloat16_as_ushort(fl);
            }
        }
        __syncthreads();

        // --- S = (Q*sc) . K^T  (tf32, 8 x k8) ---
        float sacc[8][4] = {};
        #pragma unroll
        for (int ks = 0; ks < 8; ks++) {
            const int kb = ks * 8 + t;
            uint32_t bf[8][2];
            #pragma unroll
            for (int nf = 0; nf < 8; nf++) {
                int n = 8 * nf + g;
                bf[nf][0] = Kt[n * KT_LDS + kb];
                bf[nf][1] = Kt[n * KT_LDS + kb + 4];
            }
            #pragma unroll
            for (int nf = 0; nf < 8; nf++)
                mma_tf32(sacc[nf], Qt[ks], bf[nf]);
        }

        // --- causal mask (diagonal tile only) ---
        if (jt == diag) {
            #pragma unroll
            for (int nf = 0; nf < 8; nf++) {
                int col = j0 + 8 * nf + 2 * t;
                if (col > r0)     sacc[nf][0] = -1e30f;
                if (col + 1 > r0) sacc[nf][1] = -1e30f;
                if (col > r0 + 8)     sacc[nf][2] = -1e30f;
                if (col + 1 > r0 + 8) sacc[nf][3] = -1e30f;
            }
        }

        // --- online softmax ---
        #pragma unroll
        for (int hh = 0; hh < 2; hh++) {
            float tmax = -1e30f;
            #pragma unroll
            for (int nf = 0; nf < 8; nf++)
                tmax = fmaxf(tmax, fmaxf(sacc[nf][2 * hh], sacc[nf][2 * hh + 1]));
            tmax = fmaxf(tmax, __shfl_xor_sync(0xFFFFFFFF, tmax, 1));
            tmax = fmaxf(tmax, __shfl_xor_sync(0xFFFFFFFF, tmax, 2));
            float mnew = fmaxf(mrow[hh], tmax);
            float alpha = __expf(mrow[hh] - mnew);
            mrow[hh] = mnew;
            float psum = 0.f;
            #pragma unroll
            for (int nf = 0; nf < 8; nf++) {
                float p0 = __expf(sacc[nf][2 * hh] - mnew);
                float p1 = __expf(sacc[nf][2 * hh + 1] - mnew);
                sacc[nf][2 * hh] = p0;
                sacc[nf][2 * hh + 1] = p1;
                psum += p0 + p1;
            }
            psum += __shfl_xor_sync(0xFFFFFFFF, psum, 1);
            psum += __shfl_xor_sync(0xFFFFFFFF, psum, 2);
            lrow[hh] = lrow[hh] * alpha + psum;
            #pragma unroll
            for (int nf = 0; nf < 8; nf++) {
                oacc[nf][2 * hh] *= alpha;
                oacc[nf][2 * hh + 1] *= alpha;
            }
        }

        // --- pack P (S-acc layout == bf16 k16 A-frag layout) ---
        uint32_t Ph[4][4], Pl[4][4];
        #pragma unroll
        for (int ks2 = 0; ks2 < 4; ks2++) {
            split2(sacc[2 * ks2][0], sacc[2 * ks2][1], Ph[ks2][0], Pl[ks2][0]);
            split2(sacc[2 * ks2][2], sacc[2 * ks2][3], Ph[ks2][1], Pl[ks2][1]);
            split2(sacc[2 * ks2 + 1][0], sacc[2 * ks2 + 1][1], Ph[ks2][2], Pl[ks2][2]);
            split2(sacc[2 * ks2 + 1][2], sacc[2 * ks2 + 1][3], Ph[ks2][3], Pl[ks2][3]);
        }

        // --- O += P . V  (bf16x3) ---
        #pragma unroll
        for (int ks2 = 0; ks2 < 4; ks2++) {
            uint32_t vfh[8][2], vfl[8][2];
            int kb = 16 * ks2 + 2 * t;
            #pragma unroll
            for (int nf = 0; nf < 8; nf++) {
                int n = 8 * nf + g;
                vfh[nf][0] = *(const uint32_t*)&Vsh[n * AK_LDS + kb];
                vfh[nf][1] = *(const uint32_t*)&Vsh[n * AK_LDS + kb + 8];
                vfl[nf][0] = *(const uint32_t*)&Vsl[n * AK_LDS + kb];
                vfl[nf][1] = *(const uint32_t*)&Vsl[n * AK_LDS + kb + 8];
            }
            #pragma unroll
            for (int nf = 0; nf < 8; nf++) {
                mma_bf16(oacc[nf], Ph[ks2], vfh[nf]);
                mma_bf16(oacc[nf], Ph[ks2], vfl[nf]);
                mma_bf16(oacc[nf], Pl[ks2], vfh[nf]);
            }
        }
    }

    const int b = bh / HH;
    const int h = bh % HH;
    #pragma unroll
    for (int hh = 0; hh < 2; hh++) {
        float inv = 1.f / lrow[hh];
        int row = r0 + 8 * hh;
        float* yp = g_Y + ((size_t)(b * TT) + row) * CC + h * DD;
        #pragma unroll
        for (int nf = 0; nf < 8; nf++) {
            float2 v;
            v.x = oacc[nf][2 * hh] * inv;
            v.y = oacc[nf][2 * hh + 1] * inv;
            *(float2*)(yp + 8 * nf + 2 * t) = v;
        }
    }
}

// ---------------------------------------------------------------------------
extern "C" void kernel_launch(void* const* d_in, const int* in_sizes, int n_in,
                              void* d_out, int out_size) {
    const float* x      = (const float*)d_in[0];
    const float* W_qkv  = (const float*)d_in[1];
    const float* b_qkv  = (const float*)d_in[2];
    const float* W_proj = (const float*)d_in[3];
    const float* b_proj = (const float*)d_in[4];
    float* out = (float*)d_out;

    cudaFuncSetAttribute(gemm_mma_kernel<3 * CC, 0>,
                         cudaFuncAttributeMaxDynamicSharedMemorySize, GM_SMEM_BYTES);
    cudaFuncSetAttribute(gemm_mma_kernel<CC, 1>,
                         cudaFuncAttributeMaxDynamicSharedMemorySize, GM_SMEM_BYTES);

    dim3 g1(3 * CC / GM_BN, (BB * TT) / GM_BM);   // (24, 32)
    gemm_mma_kernel<3 * CC, 0><<<g1, 256, GM_SMEM_BYTES>>>(x, W_qkv, b_qkv, nullptr);

    dim3 g2(TT / 64, BB * HH);                    // (32, 32)
    attn_mma_kernel<<<g2, 128>>>();

    dim3 g3(CC / GM_BN, (BB * TT) / GM_BM);       // (8, 32)
    gemm_mma_kernel<CC, 1><<<g3, 256, GM_SMEM_BYTES>>>(nullptr, W_proj, b_proj, out);
}

// round 12
// speedup vs baseline: 1.2302x; 1.2302x over previous
#include <cuda_runtime.h>
#include <cuda_bf16.h>
#include <cstdint>

// Problem constants
#define BB 2
#define TT 2048
#define CC 1024
#define HH 16
#define DD 64

// Scratch (allocation-free rule: __device__ globals)
__device__ float g_Q[BB * HH * TT * DD];   // [B,H,T,D]
__device__ float g_K[BB * HH * TT * DD];
__device__ float g_V[BB * HH * TT * DD];
__device__ float g_Y[BB * TT * CC];        // attention output, [B,T,C]

__device__ __forceinline__ void mma_bf16(float (&c)[4], const uint32_t (&a)[4],
                                         const uint32_t (&b)[2]) {
    asm volatile(
        "mma.sync.aligned.m16n8k16.row.col.f32.bf16.bf16.f32 "
        "{%0,%1,%2,%3}, {%4,%5,%6,%7}, {%8,%9}, {%0,%1,%2,%3};"
        : "+f"(c[0]), "+f"(c[1]), "+f"(c[2]), "+f"(c[3])
        : "r"(a[0]), "r"(a[1]), "r"(a[2]), "r"(a[3]), "r"(b[0]), "r"(b[1]));
}

__device__ __forceinline__ void mma_tf32(float (&c)[4], const uint32_t (&a)[4],
                                         const uint32_t (&b)[2]) {
    asm volatile(
        "mma.sync.aligned.m16n8k8.row.col.f32.tf32.tf32.f32 "
        "{%0,%1,%2,%3}, {%4,%5,%6,%7}, {%8,%9}, {%0,%1,%2,%3};"
        : "+f"(c[0]), "+f"(c[1]), "+f"(c[2]), "+f"(c[3])
        : "r"(a[0]), "r"(a[1]), "r"(a[2]), "r"(a[3]), "r"(b[0]), "r"(b[1]));
}

__device__ __forceinline__ float to_tf32(float x) {
    float r;
    asm("cvt.rna.tf32.f32 %0, %1;" : "=f"(r) : "f"(x));
    return r;
}

// split (x0, x1) into packed bf16 hi pair + lo pair (x0 in low half)
__device__ __forceinline__ void split2(float x0, float x1, uint32_t& hi, uint32_t& lo) {
    __nv_bfloat16 h0 = __float2bfloat16_rn(x0);
    __nv_bfloat16 h1 = __float2bfloat16_rn(x1);
    __nv_bfloat16 l0 = __float2bfloat16_rn(x0 - __bfloat162float(h0));
    __nv_bfloat16 l1 = __float2bfloat16_rn(x1 - __bfloat162float(h1));
    hi = (uint32_t)__bfloat16_as_ushort(h1) << 16 | __bfloat16_as_ushort(h0);
    lo = (uint32_t)__bfloat16_as_ushort(l1) << 16 | __bfloat16_as_ushort(l0);
}

// ---------------------------------------------------------------------------
// tf32 mma.sync GEMM (R9 exact: single buffer, 2 CTAs/SM).
// ---------------------------------------------------------------------------
#define GM_BM 128
#define GM_BN 128
#define GM_BK 32
#define GM_LDS 36
#define GM_NKT (CC / GM_BK)  // 32

template <int NN, int MODE>
__global__ __launch_bounds__(256, 2) void gemm_mma_kernel(
    const float* __restrict__ Ain, const float* __restrict__ W,
    const float* __restrict__ bias, float* __restrict__ out) {
    __shared__ __align__(16) uint32_t As[GM_BM * GM_LDS];
    __shared__ __align__(16) uint32_t Bs[GM_BN * GM_LDS];

    const float* __restrict__ A = (MODE == 1) ? (const float*)g_Y : Ain;

    const int tid = threadIdx.x;
    const int lane = tid & 31;
    const int warp = tid >> 5;
    const int wm = warp & 1;
    const int wn = warp >> 1;
    const int g = lane >> 2;
    const int t = lane & 3;
    const int m0 = blockIdx.y * GM_BM;
    const int n0 = blockIdx.x * GM_BN;

    const int nB = tid & 127;
    const int khB = tid >> 7;

    float4 ar[4];
    float brg[4][4];

    #pragma unroll
    for (int i = 0; i < 4; i++) {
        int idx = tid + i * 256;
        ar[i] = *(const float4*)(A + (size_t)(m0 + (idx >> 3)) * CC + ((idx & 7) << 2));
        const float* wp = W + (size_t)(khB * 16 + i * 4) * NN + n0 + nB;
        brg[i][0] = wp[0];
        brg[i][1] = wp[NN];
        brg[i][2] = wp[2 * NN];
        brg[i][3] = wp[3 * NN];
    }

    float acc[4][4][4] = {};

    #pragma unroll 1
    for (int kt = 0; kt < GM_NKT; kt++) {
        __syncthreads();
        #pragma unroll
        for (int i = 0; i < 4; i++) {
            int idx = tid + i * 256;
            int am = idx >> 3, akq = (idx & 7) << 2;
            uint4 u;
            u.x = __float_as_uint(to_tf32(ar[i].x));
            u.y = __float_as_uint(to_tf32(ar[i].y));
            u.z = __float_as_uint(to_tf32(ar[i].z));
            u.w = __float_as_uint(to_tf32(ar[i].w));
            *(uint4*)&As[am * GM_LDS + akq] = u;
            uint4 w;
            w.x = __float_as_uint(to_tf32(brg[i][0]));
            w.y = __float_as_uint(to_tf32(brg[i][1]));
            w.z = __float_as_uint(to_tf32(brg[i][2]));
            w.w = __float_as_uint(to_tf32(brg[i][3]));
            *(uint4*)&Bs[nB * GM_LDS + khB * 16 + i * 4] = w;
        }
        __syncthreads();

        if (kt + 1 < GM_NKT) {
            const int k0 = (kt + 1) * GM_BK;
            #pragma unroll
            for (int i = 0; i < 4; i++) {
                int idx = tid + i * 256;
                ar[i] = *(const float4*)(A + (size_t)(m0 + (idx >> 3)) * CC + k0 + ((idx & 7) << 2));
                const float* wp = W + (size_t)(k0 + khB * 16 + i * 4) * NN + n0 + nB;
                brg[i][0] = wp[0];
                brg[i][1] = wp[NN];
                brg[i][2] = wp[2 * NN];
                brg[i][3] = wp[3 * NN];
            }
        }

        #pragma unroll
        for (int ks = 0; ks < 4; ks++) {
            const int kb = ks * 8 + t;
            uint32_t af[4][4], bf[4][2];
            #pragma unroll
            for (int mf = 0; mf < 4; mf++) {
                int m = wm * 64 + mf * 16 + g;
                af[mf][0] = As[m * GM_LDS + kb];
                af[mf][1] = As[(m + 8) * GM_LDS + kb];
                af[mf][2] = As[m * GM_LDS + kb + 4];
                af[mf][3] = As[(m + 8) * GM_LDS + kb + 4];
            }
            #pragma unroll
            for (int nf = 0; nf < 4; nf++) {
                int n = wn * 32 + nf * 8 + g;
                bf[nf][0] = Bs[n * GM_LDS + kb];
                bf[nf][1] = Bs[n * GM_LDS + kb + 4];
            }
            #pragma unroll
            for (int mf = 0; mf < 4; mf++)
                #pragma unroll
                for (int nf = 0; nf < 4; nf++)
                    mma_tf32(acc[mf][nf], af[mf], bf[nf]);
        }
    }

    #pragma unroll
    for (int mf = 0; mf < 4; mf++) {
        #pragma unroll
        for (int half = 0; half < 2; half++) {
            int row = m0 + wm * 64 + mf * 16 + g + half * 8;
            #pragma unroll
            for (int nf = 0; nf < 4; nf++) {
                int col = n0 + wn * 32 + nf * 8 + 2 * t;
                float2 v;
                v.x = acc[mf][nf][2 * half + 0] + bias[col];
                v.y = acc[mf][nf][2 * half + 1] + bias[col + 1];
                if (MODE == 0) {
                    int which = col / CC;
                    int c2 = col % CC;
                    int h = c2 / DD, d = c2 % DD;
                    int b = row / TT, tt = row % TT;
                    float* base = (which == 0) ? g_Q : (which == 1) ? g_K : g_V;
                    *(float2*)(base + (((size_t)(b * HH + h) * TT + tt) * DD + d)) = v;
                } else {
                    *(float2*)(out + (size_t)row * NN + col) = v;
                }
            }
        }
    }
}

// ---------------------------------------------------------------------------
// Tensor-core flash attention: tf32 QK^T + bf16x3 PV (full precision, R9
// numerics), V staged as pair-packed uint32 (STS.128, conflict-light).
// CTA: 128 threads / 4 warps / 64 q-rows, key tiles 64, longest-first.
// ---------------------------------------------------------------------------
#define KT_LDS 76   // uint32 stride for K (frag bank = (12g+t)%32, bijective)
#define VP_LDS 72   // uint32 stride for V pairs (frag bank = 8t+g, bijective)

__global__ __launch_bounds__(128) void attn_mma_kernel() {
    __shared__ __align__(16) uint32_t Kt[64 * KT_LDS];    // [key][d] tf32
    __shared__ __align__(16) uint32_t Vph[32 * VP_LDS];   // [key_pair][d] bf16x2 hi
    __shared__ __align__(16) uint32_t Vpl[32 * VP_LDS];   // [key_pair][d] bf16x2 lo

    const int bh = blockIdx.y;
    const int bx = gridDim.x - 1 - blockIdx.x;   // longest rows first
    const int qm0 = bx * 64;
    const int tid = threadIdx.x;
    const int lane = tid & 31;
    const int warp = tid >> 5;                   // 0..3
    const int g = lane >> 2;
    const int t = lane & 3;

    const float* Qb = g_Q + (size_t)bh * TT * DD;
    const float* Kb = g_K + (size_t)bh * TT * DD;
    const float* Vb = g_V + (size_t)bh * TT * DD;

    // --- Q as tf32 A-fragments (scale folded): 8 k8-chunks x 4 regs ---
    const int r0 = qm0 + warp * 16 + g;
    const float* q0p = Qb + (size_t)r0 * DD;
    const float* q1p = q0p + 8 * DD;
    const float sc = 0.125f;
    uint32_t Qt[8][4];
    #pragma unroll
    for (int ks = 0; ks < 8; ks++) {
        int d0 = ks * 8 + t;
        Qt[ks][0] = __float_as_uint(to_tf32(q0p[d0] * sc));
        Qt[ks][1] = __float_as_uint(to_tf32(q1p[d0] * sc));
        Qt[ks][2] = __float_as_uint(to_tf32(q0p[d0 + 4] * sc));
        Qt[ks][3] = __float_as_uint(to_tf32(q1p[d0 + 4] * sc));
    }

    float oacc[8][4] = {};
    float mrow[2] = {-1e30f, -1e30f};
    float lrow[2] = {0.f, 0.f};

    const int ntiles = bx + 1;
    const int diag = bx;   // only the last tile is masked

    // V staging decomposition: lane -> (half, dg)
    const int vhalf = lane >> 4;    // 0..1
    const int vdg = lane & 15;      // d-group (4 floats)

    #pragma unroll 1
    for (int jt = 0; jt < ntiles; jt++) {
        const int j0 = jt * 64;
        __syncthreads();
        // --- K tile [key][d] tf32 (STS.128) ---
        #pragma unroll
        for (int p = 0; p < 8; p++) {
            int idx = tid + p * 128;
            int key = idx >> 4;
            int d = (idx & 15) << 2;
            float4 kv = *(const float4*)(Kb + (size_t)(j0 + key) * DD + d);
            uint4 u;
            u.x = __float_as_uint(to_tf32(kv.x));
            u.y = __float_as_uint(to_tf32(kv.y));
            u.z = __float_as_uint(to_tf32(kv.z));
            u.w = __float_as_uint(to_tf32(kv.w));
            *(uint4*)&Kt[key * KT_LDS + d] = u;
        }
        // --- V tile: pair-packed [key_pair][d], hi/lo, STS.128 ---
        #pragma unroll
        for (int q = 0; q < 4; q++) {
            int kp = q * 8 + warp * 2 + vhalf;      // 0..31
            const float* vp = Vb + (size_t)(j0 + 2 * kp) * DD + 4 * vdg;
            float4 v0 = *(const float4*)(vp);
            float4 v1 = *(const float4*)(vp + DD);
            uint4 hw, lw;
            split2(v0.x, v1.x, hw.x, lw.x);
            split2(v0.y, v1.y, hw.y, lw.y);
            split2(v0.z, v1.z, hw.z, lw.z);
            split2(v0.w, v1.w, hw.w, lw.w);
            *(uint4*)&Vph[kp * VP_LDS + 4 * vdg] = hw;
            *(uint4*)&Vpl[kp * VP_LDS + 4 * vdg] = lw;
        }
        __syncthreads();

        // --- S = (Q*sc) . K^T  (tf32, 8 x k8) ---
        float sacc[8][4] = {};
        #pragma unroll
        for (int ks = 0; ks < 8; ks++) {
            const int kb = ks * 8 + t;
            uint32_t bf[8][2];
            #pragma unroll
            for (int nf = 0; nf < 8; nf++) {
                int n = 8 * nf + g;
                bf[nf][0] = Kt[n * KT_LDS + kb];
                bf[nf][1] = Kt[n * KT_LDS + kb + 4];
            }
            #pragma unroll
            for (int nf = 0; nf < 8; nf++)
                mma_tf32(sacc[nf], Qt[ks], bf[nf]);
        }

        // --- causal mask (diagonal tile only) ---
        if (jt == diag) {
            #pragma unroll
            for (int nf = 0; nf < 8; nf++) {
                int col = j0 + 8 * nf + 2 * t;
                if (col > r0)     sacc[nf][0] = -1e30f;
                if (col + 1 > r0) sacc[nf][1] = -1e30f;
                if (col > r0 + 8)     sacc[nf][2] = -1e30f;
                if (col + 1 > r0 + 8) sacc[nf][3] = -1e30f;
            }
        }

        // --- online softmax ---
        #pragma unroll
        for (int hh = 0; hh < 2; hh++) {
            float tmax = -1e30f;
            #pragma unroll
            for (int nf = 0; nf < 8; nf++)
                tmax = fmaxf(tmax, fmaxf(sacc[nf][2 * hh], sacc[nf][2 * hh + 1]));
            tmax = fmaxf(tmax, __shfl_xor_sync(0xFFFFFFFF, tmax, 1));
            tmax = fmaxf(tmax, __shfl_xor_sync(0xFFFFFFFF, tmax, 2));
            float mnew = fmaxf(mrow[hh], tmax);
            float alpha = __expf(mrow[hh] - mnew);
            mrow[hh] = mnew;
            float psum = 0.f;
            #pragma unroll
            for (int nf = 0; nf < 8; nf++) {
                float p0 = __expf(sacc[nf][2 * hh] - mnew);
                float p1 = __expf(sacc[nf][2 * hh + 1] - mnew);
                sacc[nf][2 * hh] = p0;
                sacc[nf][2 * hh + 1] = p1;
                psum += p0 + p1;
            }
            psum += __shfl_xor_sync(0xFFFFFFFF, psum, 1);
            psum += __shfl_xor_sync(0xFFFFFFFF, psum, 2);
            lrow[hh] = lrow[hh] * alpha + psum;
            #pragma unroll
            for (int nf = 0; nf < 8; nf++) {
                oacc[nf][2 * hh] *= alpha;
                oacc[nf][2 * hh + 1] *= alpha;
            }
        }

        // --- pack P hi/lo (S-acc layout == bf16 k16 A-frag layout) ---
        uint32_t Ph[4][4], Pl[4][4];
        #pragma unroll
        for (int ks2 = 0; ks2 < 4; ks2++) {
            split2(sacc[2 * ks2][0], sacc[2 * ks2][1], Ph[ks2][0], Pl[ks2][0]);
            split2(sacc[2 * ks2][2], sacc[2 * ks2][3], Ph[ks2][1], Pl[ks2][1]);
            split2(sacc[2 * ks2 + 1][0], sacc[2 * ks2 + 1][1], Ph[ks2][2], Pl[ks2][2]);
            split2(sacc[2 * ks2 + 1][2], sacc[2 * ks2 + 1][3], Ph[ks2][3], Pl[ks2][3]);
        }

        // --- O += P . V  (bf16x3; pair-packed V fragment loads) ---
        #pragma unroll
        for (int ks2 = 0; ks2 < 4; ks2++) {
            uint32_t vfh[8][2], vfl[8][2];
            const int kq = 8 * ks2 + t;
            #pragma unroll
            for (int nf = 0; nf < 8; nf++) {
                int n = 8 * nf + g;
                vfh[nf][0] = Vph[kq * VP_LDS + n];
                vfh[nf][1] = Vph[(kq + 4) * VP_LDS + n];
                vfl[nf][0] = Vpl[kq * VP_LDS + n];
                vfl[nf][1] = Vpl[(kq + 4) * VP_LDS + n];
            }
            #pragma unroll
            for (int nf = 0; nf < 8; nf++) {
                mma_bf16(oacc[nf], Ph[ks2], vfh[nf]);
                mma_bf16(oacc[nf], Ph[ks2], vfl[nf]);
                mma_bf16(oacc[nf], Pl[ks2], vfh[nf]);
            }
        }
    }

    const int b = bh / HH;
    const int h = bh % HH;
    #pragma unroll
    for (int hh = 0; hh < 2; hh++) {
        float inv = 1.f / lrow[hh];
        int row = r0 + 8 * hh;
        float* yp = g_Y + ((size_t)(b * TT) + row) * CC + h * DD;
        #pragma unroll
        for (int nf = 0; nf < 8; nf++) {
            float2 v;
            v.x = oacc[nf][2 * hh] * inv;
            v.y = oacc[nf][2 * hh + 1] * inv;
            *(float2*)(yp + 8 * nf + 2 * t) = v;
        }
    }
}

// ---------------------------------------------------------------------------
extern "C" void kernel_launch(void* const* d_in, const int* in_sizes, int n_in,
                              void* d_out, int out_size) {
    const float* x      = (const float*)d_in[0];
    const float* W_qkv  = (const float*)d_in[1];
    const float* b_qkv  = (const float*)d_in[2];
    const float* W_proj = (const float*)d_in[3];
    const float* b_proj = (const float*)d_in[4];
    float* out = (float*)d_out;

    dim3 g1(3 * CC / GM_BN, (BB * TT) / GM_BM);   // (24, 32)
    gemm_mma_kernel<3 * CC, 0><<<g1, 256>>>(x, W_qkv, b_qkv, nullptr);

    dim3 g2(TT / 64, BB * HH);                    // (32, 32)
    attn_mma_kernel<<<g2, 128>>>();

    dim3 g3(CC / GM_BN, (BB * TT) / GM_BM);       // (8, 32)
    gemm_mma_kernel<CC, 1><<<g3, 256>>>(nullptr, W_proj, b_proj, out);
}

// round 14
// speedup vs baseline: 1.2709x; 1.0331x over previous
#include <cuda_runtime.h>
#include <cuda_bf16.h>
#include <cstdint>

// Problem constants
#define BB 2
#define TT 2048
#define CC 1024
#define HH 16
#define DD 64

// Scratch (allocation-free rule: __device__ globals)
__device__ float g_Q[BB * HH * TT * DD];   // [B,H,T,D]
__device__ float g_K[BB * HH * TT * DD];
__device__ float g_V[BB * HH * TT * DD];
__device__ float g_Y[BB * TT * CC];        // attention output, [B,T,C]

__device__ __forceinline__ void mma_tf32(float (&c)[4], const uint32_t (&a)[4],
                                         const uint32_t (&b)[2]) {
    asm volatile(
        "mma.sync.aligned.m16n8k8.row.col.f32.tf32.tf32.f32 "
        "{%0,%1,%2,%3}, {%4,%5,%6,%7}, {%8,%9}, {%0,%1,%2,%3};"
        : "+f"(c[0]), "+f"(c[1]), "+f"(c[2]), "+f"(c[3])
        : "r"(a[0]), "r"(a[1]), "r"(a[2]), "r"(a[3]), "r"(b[0]), "r"(b[1]));
}

__device__ __forceinline__ float to_tf32(float x) {
    float r;
    asm("cvt.rna.tf32.f32 %0, %1;" : "=f"(r) : "f"(x));
    return r;
}

// ---------------------------------------------------------------------------
// tf32 mma.sync GEMM (R9/R12 exact: single buffer, 2 CTAs/SM).
// ---------------------------------------------------------------------------
#define GM_BM 128
#define GM_BN 128
#define GM_BK 32
#define GM_LDS 36
#define GM_NKT (CC / GM_BK)  // 32

template <int NN, int MODE>
__global__ __launch_bounds__(256, 2) void gemm_mma_kernel(
    const float* __restrict__ Ain, const float* __restrict__ W,
    const float* __restrict__ bias, float* __restrict__ out) {
    __shared__ __align__(16) uint32_t As[GM_BM * GM_LDS];
    __shared__ __align__(16) uint32_t Bs[GM_BN * GM_LDS];

    const float* __restrict__ A = (MODE == 1) ? (const float*)g_Y : Ain;

    const int tid = threadIdx.x;
    const int lane = tid & 31;
    const int warp = tid >> 5;
    const int wm = warp & 1;
    const int wn = warp >> 1;
    const int g = lane >> 2;
    const int t = lane & 3;
    const int m0 = blockIdx.y * GM_BM;
    const int n0 = blockIdx.x * GM_BN;

    const int nB = tid & 127;
    const int khB = tid >> 7;

    float4 ar[4];
    float brg[4][4];

    #pragma unroll
    for (int i = 0; i < 4; i++) {
        int idx = tid + i * 256;
        ar[i] = *(const float4*)(A + (size_t)(m0 + (idx >> 3)) * CC + ((idx & 7) << 2));
        const float* wp = W + (size_t)(khB * 16 + i * 4) * NN + n0 + nB;
        brg[i][0] = wp[0];
        brg[i][1] = wp[NN];
        brg[i][2] = wp[2 * NN];
        brg[i][3] = wp[3 * NN];
    }

    float acc[4][4][4] = {};

    #pragma unroll 1
    for (int kt = 0; kt < GM_NKT; kt++) {
        __syncthreads();
        #pragma unroll
        for (int i = 0; i < 4; i++) {
            int idx = tid + i * 256;
            int am = idx >> 3, akq = (idx & 7) << 2;
            uint4 u;
            u.x = __float_as_uint(to_tf32(ar[i].x));
            u.y = __float_as_uint(to_tf32(ar[i].y));
            u.z = __float_as_uint(to_tf32(ar[i].z));
            u.w = __float_as_uint(to_tf32(ar[i].w));
            *(uint4*)&As[am * GM_LDS + akq] = u;
            uint4 w;
            w.x = __float_as_uint(to_tf32(brg[i][0]));
            w.y = __float_as_uint(to_tf32(brg[i][1]));
            w.z = __float_as_uint(to_tf32(brg[i][2]));
            w.w = __float_as_uint(to_tf32(brg[i][3]));
            *(uint4*)&Bs[nB * GM_LDS + khB * 16 + i * 4] = w;
        }
        __syncthreads();

        if (kt + 1 < GM_NKT) {
            const int k0 = (kt + 1) * GM_BK;
            #pragma unroll
            for (int i = 0; i < 4; i++) {
                int idx = tid + i * 256;
                ar[i] = *(const float4*)(A + (size_t)(m0 + (idx >> 3)) * CC + k0 + ((idx & 7) << 2));
                const float* wp = W + (size_t)(k0 + khB * 16 + i * 4) * NN + n0 + nB;
                brg[i][0] = wp[0];
                brg[i][1] = wp[NN];
                brg[i][2] = wp[2 * NN];
                brg[i][3] = wp[3 * NN];
            }
        }

        #pragma unroll
        for (int ks = 0; ks < 4; ks++) {
            const int kb = ks * 8 + t;
            uint32_t af[4][4], bf[4][2];
            #pragma unroll
            for (int mf = 0; mf < 4; mf++) {
                int m = wm * 64 + mf * 16 + g;
                af[mf][0] = As[m * GM_LDS + kb];
                af[mf][1] = As[(m + 8) * GM_LDS + kb];
                af[mf][2] = As[m * GM_LDS + kb + 4];
                af[mf][3] = As[(m + 8) * GM_LDS + kb + 4];
            }
            #pragma unroll
            for (int nf = 0; nf < 4; nf++) {
                int n = wn * 32 + nf * 8 + g;
                bf[nf][0] = Bs[n * GM_LDS + kb];
                bf[nf][1] = Bs[n * GM_LDS + kb + 4];
            }
            #pragma unroll
            for (int mf = 0; mf < 4; mf++)
                #pragma unroll
                for (int nf = 0; nf < 4; nf++)
                    mma_tf32(acc[mf][nf], af[mf], bf[nf]);
        }
    }

    #pragma unroll
    for (int mf = 0; mf < 4; mf++) {
        #pragma unroll
        for (int half = 0; half < 2; half++) {
            int row = m0 + wm * 64 + mf * 16 + g + half * 8;
            #pragma unroll
            for (int nf = 0; nf < 4; nf++) {
                int col = n0 + wn * 32 + nf * 8 + 2 * t;
                float2 v;
                v.x = acc[mf][nf][2 * half + 0] + bias[col];
                v.y = acc[mf][nf][2 * half + 1] + bias[col + 1];
                if (MODE == 0) {
                    int which = col / CC;
                    int c2 = col % CC;
                    int h = c2 / DD, d = c2 % DD;
                    int b = row / TT, tt = row % TT;
                    float* base = (which == 0) ? g_Q : (which == 1) ? g_K : g_V;
                    *(float2*)(base + (((size_t)(b * HH + h) * TT + tt) * DD + d)) = v;
                } else {
                    *(float2*)(out + (size_t)row * NN + col) = v;
                }
            }
        }
    }
}

// ---------------------------------------------------------------------------
// Tensor-core flash attention: all-tf32 (QK^T and PV).
// P gathered from S-accumulator via warp shuffles (no smem round-trip).
// CTA: 128 threads / 4 warps / 64 q-rows, key tiles 64, longest-first.
// ---------------------------------------------------------------------------
#define KT_LDS 76   // uint32 stride for K (frag bank = (12g+t)%32, bijective)
#define VT_LDS 72   // uint32 stride for V (frag bank = 8t+g, bijective)

__global__ __launch_bounds__(128) void attn_mma_kernel() {
    __shared__ __align__(16) uint32_t Kt[64 * KT_LDS];   // [key][d] tf32
    __shared__ __align__(16) uint32_t Vt[64 * VT_LDS];   // [key][d] tf32

    const int bh = blockIdx.y;
    const int bx = gridDim.x - 1 - blockIdx.x;   // longest rows first
    const int qm0 = bx * 64;
    const int tid = threadIdx.x;
    const int lane = tid & 31;
    const int warp = tid >> 5;                   // 0..3
    const int g = lane >> 2;
    const int t = lane & 3;

    const float* Qb = g_Q + (size_t)bh * TT * DD;
    const float* Kb = g_K + (size_t)bh * TT * DD;
    const float* Vb = g_V + (size_t)bh * TT * DD;

    // --- Q as tf32 A-fragments (scale folded): 8 k8-chunks x 4 regs ---
    const int r0 = qm0 + warp * 16 + g;
    const float* q0p = Qb + (size_t)r0 * DD;
    const float* q1p = q0p + 8 * DD;
    const float sc = 0.125f;
    uint32_t Qt[8][4];
    #pragma unroll
    for (int ks = 0; ks < 8; ks++) {
        int d0 = ks * 8 + t;
        Qt[ks][0] = __float_as_uint(to_tf32(q0p[d0] * sc));
        Qt[ks][1] = __float_as_uint(to_tf32(q1p[d0] * sc));
        Qt[ks][2] = __float_as_uint(to_tf32(q0p[d0 + 4] * sc));
        Qt[ks][3] = __float_as_uint(to_tf32(q1p[d0 + 4] * sc));
    }

    float oacc[8][4] = {};
    float mrow[2] = {-1e30f, -1e30f};
    float lrow[2] = {0.f, 0.f};

    const int ntiles = bx + 1;
    const int diag = bx;   // only the last tile is masked

    #pragma unroll 1
    for (int jt = 0; jt < ntiles; jt++) {
        const int j0 = jt * 64;
        __syncthreads();
        // --- K and V tiles [key][d] tf32 (STS.128, conflict-free) ---
        #pragma unroll
        for (int p = 0; p < 8; p++) {
            int idx = tid + p * 128;
            int key = idx >> 4;
            int d = (idx & 15) << 2;
            float4 kv = *(const float4*)(Kb + (size_t)(j0 + key) * DD + d);
            uint4 u;
            u.x = __float_as_uint(to_tf32(kv.x));
            u.y = __float_as_uint(to_tf32(kv.y));
            u.z = __float_as_uint(to_tf32(kv.z));
            u.w = __float_as_uint(to_tf32(kv.w));
            *(uint4*)&Kt[key * KT_LDS + d] = u;
            float4 vv = *(const float4*)(Vb + (size_t)(j0 + key) * DD + d);
            uint4 w;
            w.x = __float_as_uint(to_tf32(vv.x));
            w.y = __float_as_uint(to_tf32(vv.y));
            w.z = __float_as_uint(to_tf32(vv.z));
            w.w = __float_as_uint(to_tf32(vv.w));
            *(uint4*)&Vt[key * VT_LDS + d] = w;
        }
        __syncthreads();

        // --- S = (Q*sc) . K^T  (tf32, 8 x k8) ---
        float sacc[8][4] = {};
        #pragma unroll
        for (int ks = 0; ks < 8; ks++) {
            const int kb = ks * 8 + t;
            uint32_t bf[8][2];
            #pragma unroll
            for (int nf = 0; nf < 8; nf++) {
                int n = 8 * nf + g;
                bf[nf][0] = Kt[n * KT_LDS + kb];
                bf[nf][1] = Kt[n * KT_LDS + kb + 4];
            }
            #pragma unroll
            for (int nf = 0; nf < 8; nf++)
                mma_tf32(sacc[nf], Qt[ks], bf[nf]);
        }

        // --- causal mask (diagonal tile only) ---
        if (jt == diag) {
            #pragma unroll
            for (int nf = 0; nf < 8; nf++) {
                int col = j0 + 8 * nf + 2 * t;
                if (col > r0)     sacc[nf][0] = -1e30f;
                if (col + 1 > r0) sacc[nf][1] = -1e30f;
                if (col > r0 + 8)     sacc[nf][2] = -1e30f;
                if (col + 1 > r0 + 8) sacc[nf][3] = -1e30f;
            }
        }

        // --- online softmax ---
        #pragma unroll
        for (int hh = 0; hh < 2; hh++) {
            float tmax = -1e30f;
            #pragma unroll
            for (int nf = 0; nf < 8; nf++)
                tmax = fmaxf(tmax, fmaxf(sacc[nf][2 * hh], sacc[nf][2 * hh + 1]));
            tmax = fmaxf(tmax, __shfl_xor_sync(0xFFFFFFFF, tmax, 1));
            tmax = fmaxf(tmax, __shfl_xor_sync(0xFFFFFFFF, tmax, 2));
            float mnew = fmaxf(mrow[hh], tmax);
            float alpha = __expf(mrow[hh] - mnew);
            mrow[hh] = mnew;
            float psum = 0.f;
            #pragma unroll
            for (int nf = 0; nf < 8; nf++) {
                float p0 = __expf(sacc[nf][2 * hh] - mnew);
                float p1 = __expf(sacc[nf][2 * hh + 1] - mnew);
                sacc[nf][2 * hh] = p0;
                sacc[nf][2 * hh + 1] = p1;
                psum += p0 + p1;
            }
            psum += __shfl_xor_sync(0xFFFFFFFF, psum, 1);
            psum += __shfl_xor_sync(0xFFFFFFFF, psum, 2);
            lrow[hh] = lrow[hh] * alpha + psum;
            #pragma unroll
            for (int nf = 0; nf < 8; nf++) {
                oacc[nf][2 * hh] *= alpha;
                oacc[nf][2 * hh + 1] *= alpha;
            }
        }

        // --- O += P . V  (tf32; P A-fragments gathered via shuffles) ---
        // sacc C-layout: thread (g,t) holds P[g..g+8][8*nf + 2t, 2t+1].
        // A-frag needs P[g][8*ks2 + t]: source lane g*4 + (t>>1), reg parity t&1.
        const int src0 = (lane & 28) | (t >> 1);
        const int src1 = src0 + 2;
        const int rsel = t & 1;
        #pragma unroll
        for (int ks2 = 0; ks2 < 8; ks2++) {
            uint32_t af[4];
            {
                float x0 = __shfl_sync(0xFFFFFFFF, sacc[ks2][0], src0);
                float x1 = __shfl_sync(0xFFFFFFFF, sacc[ks2][1], src0);
                af[0] = __float_as_uint(rsel ? x1 : x0);
                float y0 = __shfl_sync(0xFFFFFFFF, sacc[ks2][2], src0);
                float y1 = __shfl_sync(0xFFFFFFFF, sacc[ks2][3], src0);
                af[1] = __float_as_uint(rsel ? y1 : y0);
                float z0 = __shfl_sync(0xFFFFFFFF, sacc[ks2][0], src1);
                float z1 = __shfl_sync(0xFFFFFFFF, sacc[ks2][1], src1);
                af[2] = __float_as_uint(rsel ? z1 : z0);
                float w0 = __shfl_sync(0xFFFFFFFF, sacc[ks2][2], src1);
                float w1 = __shfl_sync(0xFFFFFFFF, sacc[ks2][3], src1);
                af[3] = __float_as_uint(rsel ? w1 : w0);
            }
            const int kb = ks2 * 8 + t;
            uint32_t bf[8][2];
            #pragma unroll
            for (int nf = 0; nf < 8; nf++) {
                int n = 8 * nf + g;
                bf[nf][0] = Vt[kb * VT_LDS + n];
                bf[nf][1] = Vt[(kb + 4) * VT_LDS + n];
            }
            #pragma unroll
            for (int nf = 0; nf < 8; nf++)
                mma_tf32(oacc[nf], af, bf[nf]);
        }
    }

    const int b = bh / HH;
    const int h = bh % HH;
    #pragma unroll
    for (int hh = 0; hh < 2; hh++) {
        float inv = 1.f / lrow[hh];
        int row = r0 + 8 * hh;
        float* yp = g_Y + ((size_t)(b * TT) + row) * CC + h * DD;
        #pragma unroll
        for (int nf = 0; nf < 8; nf++) {
            float2 v;
            v.x = oacc[nf][2 * hh] * inv;
            v.y = oacc[nf][2 * hh + 1] * inv;
            *(float2*)(yp + 8 * nf + 2 * t) = v;
        }
    }
}

// ---------------------------------------------------------------------------
extern "C" void kernel_launch(void* const* d_in, const int* in_sizes, int n_in,
                              void* d_out, int out_size) {
    const float* x      = (const float*)d_in[0];
    const float* W_qkv  = (const float*)d_in[1];
    const float* b_qkv  = (const float*)d_in[2];
    const float* W_proj = (const float*)d_in[3];
    const float* b_proj = (const float*)d_in[4];
    float* out = (float*)d_out;

    dim3 g1(3 * CC / GM_BN, (BB * TT) / GM_BM);   // (24, 32)
    gemm_mma_kernel<3 * CC, 0><<<g1, 256>>>(x, W_qkv, b_qkv, nullptr);

    dim3 g2(TT / 64, BB * HH);                    // (32, 32)
    attn_mma_kernel<<<g2, 128>>>();

    dim3 g3(CC / GM_BN, (BB * TT) / GM_BM);       // (8, 32)
    gemm_mma_kernel<CC, 1><<<g3, 256>>>(nullptr, W_proj, b_proj, out);
}

// round 15
// speedup vs baseline: 1.3733x; 1.0806x over previous
#include <cuda_runtime.h>
#include <cstdint>

// Problem constants
#define BB 2
#define TT 2048
#define CC 1024
#define HH 16
#define DD 64

// Scratch (allocation-free rule: __device__ globals)
__device__ float g_Q[BB * HH * TT * DD];   // [B,H,T,D]
__device__ float g_K[BB * HH * TT * DD];
__device__ float g_V[BB * HH * TT * DD];
__device__ float g_Y[BB * TT * CC];        // attention output (pre-rounded tf32)
__device__ float g_X[BB * TT * CC];        // x pre-rounded to tf32
__device__ float g_Wq[CC * 3 * CC];        // W_qkv pre-rounded to tf32
__device__ float g_Wp[CC * CC];            // W_proj pre-rounded to tf32

__device__ __forceinline__ void mma_tf32(float (&c)[4], const uint32_t (&a)[4],
                                         const uint32_t (&b)[2]) {
    asm volatile(
        "mma.sync.aligned.m16n8k8.row.col.f32.tf32.tf32.f32 "
        "{%0,%1,%2,%3}, {%4,%5,%6,%7}, {%8,%9}, {%0,%1,%2,%3};"
        : "+f"(c[0]), "+f"(c[1]), "+f"(c[2]), "+f"(c[3])
        : "r"(a[0]), "r"(a[1]), "r"(a[2]), "r"(a[3]), "r"(b[0]), "r"(b[1]));
}

__device__ __forceinline__ float to_tf32(float x) {
    float r;
    asm("cvt.rna.tf32.f32 %0, %1;" : "=f"(r) : "f"(x));
    return r;
}

__device__ __forceinline__ uint32_t smem_u32(const void* p) {
    uint32_t a;
    asm("{ .reg .u64 t; cvta.to.shared.u64 t, %1; cvt.u32.u64 %0, t; }"
        : "=r"(a) : "l"(p));
    return a;
}

__device__ __forceinline__ void cp_async16(uint32_t dst, const void* src) {
    asm volatile("cp.async.cg.shared.global [%0], [%1], 16;"
                 :: "r"(dst), "l"(src));
}
#define CP_COMMIT() asm volatile("cp.async.commit_group;" ::: "memory")
#define CP_WAIT(n)  asm volatile("cp.async.wait_group %0;" :: "n"(n) : "memory")

// ---------------------------------------------------------------------------
// Pre-pass: RNA-round x / W_qkv / W_proj to tf32 once.
// ---------------------------------------------------------------------------
__global__ __launch_bounds__(256) void pre_round_kernel(
    const float4* __restrict__ x, const float4* __restrict__ wq,
    const float4* __restrict__ wp) {
    const int stride = gridDim.x * blockDim.x;
    const int i0 = blockIdx.x * blockDim.x + threadIdx.x;
    const int NX = BB * TT * CC / 4;
    const int NWQ = CC * 3 * CC / 4;
    const int NWP = CC * CC / 4;
    float4* gx = (float4*)g_X;
    float4* gq = (float4*)g_Wq;
    float4* gp = (float4*)g_Wp;
    for (int j = i0; j < NX; j += stride) {
        float4 v = x[j];
        v.x = to_tf32(v.x); v.y = to_tf32(v.y);
        v.z = to_tf32(v.z); v.w = to_tf32(v.w);
        gx[j] = v;
    }
    for (int j = i0; j < NWQ; j += stride) {
        float4 v = wq[j];
        v.x = to_tf32(v.x); v.y = to_tf32(v.y);
        v.z = to_tf32(v.z); v.w = to_tf32(v.w);
        gq[j] = v;
    }
    for (int j = i0; j < NWP; j += stride) {
        float4 v = wp[j];
        v.x = to_tf32(v.x); v.y = to_tf32(v.y);
        v.z = to_tf32(v.z); v.w = to_tf32(v.w);
        gp[j] = v;
    }
}

// ---------------------------------------------------------------------------
// tf32 mma.sync GEMM with cp.async 3-stage pipeline, 1 barrier/iteration.
// CTA 128x128, BK=32, 8 warps (2 M x 4 N), warp tile 64x32, m16n8k8.
// A smem [m][k] stride 36; B smem [k][n] stride 136 (no transpose needed).
// All operands pre-rounded to tf32 (raw copies feed the MMA exactly).
// MODE 0: A=g_X, W=g_Wq, scatter epilogue; MODE 1: A=g_Y, W=g_Wp -> out.
// ---------------------------------------------------------------------------
#define GM_BM 128
#define GM_BN 128
#define GM_BK 32
#define GM_ALD 36
#define GM_BLD 136
#define GM_NKT (CC / GM_BK)  // 32
#define GM_ASZ (GM_BM * GM_ALD)            // 4608 words
#define GM_BSZ (GM_BK * GM_BLD)            // 4352 words
#define GM_STG (GM_ASZ + GM_BSZ)           // 8960 words/stage
#define GM_SMEM_BYTES (3 * GM_STG * 4)     // 107520 B

template <int NN, int MODE>
__global__ __launch_bounds__(256, 2) void gemm_mma_kernel(
    const float* __restrict__ bias, float* __restrict__ out) {
    extern __shared__ uint32_t dsm[];

    const float* __restrict__ A = (MODE == 1) ? (const float*)g_Y : (const float*)g_X;
    const float* __restrict__ W = (MODE == 1) ? (const float*)g_Wp : (const float*)g_Wq;

    const int tid = threadIdx.x;
    const int lane = tid & 31;
    const int warp = tid >> 5;
    const int wm = warp & 1;
    const int wn = warp >> 1;
    const int g = lane >> 2;
    const int t = lane & 3;
    const int m0 = blockIdx.y * GM_BM;
    const int n0 = blockIdx.x * GM_BN;

    const uint32_t sb = smem_u32(dsm);

    // issue one k-tile's A+B via cp.async into stage s
    auto issue = [&](int s, int kt) {
        const int k0 = kt * GM_BK;
        const uint32_t abase = sb + (s * GM_STG) * 4;
        const uint32_t bbase = sb + (s * GM_STG + GM_ASZ) * 4;
        #pragma unroll
        for (int i = 0; i < 4; i++) {
            int idx = tid + i * 256;
            int arow = idx >> 3, ac = idx & 7;
            cp_async16(abase + (arow * GM_ALD + ac * 4) * 4,
                       A + (size_t)(m0 + arow) * CC + k0 + ac * 4);
            int brow = idx >> 5, bc = idx & 31;
            cp_async16(bbase + (brow * GM_BLD + bc * 4) * 4,
                       W + (size_t)(k0 + brow) * NN + n0 + bc * 4);
        }
        CP_COMMIT();
    };

    issue(0, 0);
    issue(1, 1);

    float acc[4][4][4] = {};

    #pragma unroll 1
    for (int kt = 0; kt < GM_NKT; kt++) {
        if (kt + 1 < GM_NKT) { CP_WAIT(1); } else { CP_WAIT(0); }
        __syncthreads();

        const uint32_t* As = dsm + (kt % 3) * GM_STG;
        const uint32_t* Bs = As + GM_ASZ;

        #pragma unroll
        for (int ks = 0; ks < 4; ks++) {
            const int kb = ks * 8 + t;
            uint32_t af[4][4], bf[4][2];
            #pragma unroll
            for (int mf = 0; mf < 4; mf++) {
                int m = wm * 64 + mf * 16 + g;
                af[mf][0] = As[m * GM_ALD + kb];
                af[mf][1] = As[(m + 8) * GM_ALD + kb];
                af[mf][2] = As[m * GM_ALD + kb + 4];
                af[mf][3] = As[(m + 8) * GM_ALD + kb + 4];
            }
            #pragma unroll
            for (int nf = 0; nf < 4; nf++) {
                int n = wn * 32 + nf * 8 + g;
                bf[nf][0] = Bs[kb * GM_BLD + n];
                bf[nf][1] = Bs[(kb + 4) * GM_BLD + n];
            }
            #pragma unroll
            for (int mf = 0; mf < 4; mf++)
                #pragma unroll
                for (int nf = 0; nf < 4; nf++)
                    mma_tf32(acc[mf][nf], af[mf], bf[nf]);
        }

        if (kt + 2 < GM_NKT) issue((kt + 2) % 3, kt + 2);
    }

    #pragma unroll
    for (int mf = 0; mf < 4; mf++) {
        #pragma unroll
        for (int half = 0; half < 2; half++) {
            int row = m0 + wm * 64 + mf * 16 + g + half * 8;
            #pragma unroll
            for (int nf = 0; nf < 4; nf++) {
                int col = n0 + wn * 32 + nf * 8 + 2 * t;
                float2 v;
                v.x = acc[mf][nf][2 * half + 0] + bias[col];
                v.y = acc[mf][nf][2 * half + 1] + bias[col + 1];
                if (MODE == 0) {
                    int which = col / CC;
                    int c2 = col % CC;
                    int h = c2 / DD, d = c2 % DD;
                    int b = row / TT, tt = row % TT;
                    float* base = (which == 0) ? g_Q : (which == 1) ? g_K : g_V;
                    *(float2*)(base + (((size_t)(b * HH + h) * TT + tt) * DD + d)) = v;
                } else {
                    *(float2*)(out + (size_t)row * NN + col) = v;
                }
            }
        }
    }
}

// ---------------------------------------------------------------------------
// Tensor-core flash attention: all-tf32 (R14 body; epilogue rounds g_Y).
// CTA: 128 threads / 4 warps / 64 q-rows, key tiles 64, longest-first.
// ---------------------------------------------------------------------------
#define KT_LDS 76   // uint32 stride for K (frag bank = (12g+t)%32, bijective)
#define VT_LDS 72   // uint32 stride for V (frag bank = 8t+g, bijective)

__global__ __launch_bounds__(128) void attn_mma_kernel() {
    __shared__ __align__(16) uint32_t Kt[64 * KT_LDS];   // [key][d] tf32
    __shared__ __align__(16) uint32_t Vt[64 * VT_LDS];   // [key][d] tf32

    const int bh = blockIdx.y;
    const int bx = gridDim.x - 1 - blockIdx.x;   // longest rows first
    const int qm0 = bx * 64;
    const int tid = threadIdx.x;
    const int lane = tid & 31;
    const int warp = tid >> 5;                   // 0..3
    const int g = lane >> 2;
    const int t = lane & 3;

    const float* Qb = g_Q + (size_t)bh * TT * DD;
    const float* Kb = g_K + (size_t)bh * TT * DD;
    const float* Vb = g_V + (size_t)bh * TT * DD;

    const int r0 = qm0 + warp * 16 + g;
    const float* q0p = Qb + (size_t)r0 * DD;
    const float* q1p = q0p + 8 * DD;
    const float sc = 0.125f;
    uint32_t Qt[8][4];
    #pragma unroll
    for (int ks = 0; ks < 8; ks++) {
        int d0 = ks * 8 + t;
        Qt[ks][0] = __float_as_uint(to_tf32(q0p[d0] * sc));
        Qt[ks][1] = __float_as_uint(to_tf32(q1p[d0] * sc));
        Qt[ks][2] = __float_as_uint(to_tf32(q0p[d0 + 4] * sc));
        Qt[ks][3] = __float_as_uint(to_tf32(q1p[d0 + 4] * sc));
    }

    float oacc[8][4] = {};
    float mrow[2] = {-1e30f, -1e30f};
    float lrow[2] = {0.f, 0.f};

    const int ntiles = bx + 1;
    const int diag = bx;

    #pragma unroll 1
    for (int jt = 0; jt < ntiles; jt++) {
        const int j0 = jt * 64;
        __syncthreads();
        #pragma unroll
        for (int p = 0; p < 8; p++) {
            int idx = tid + p * 128;
            int key = idx >> 4;
            int d = (idx & 15) << 2;
            float4 kv = *(const float4*)(Kb + (size_t)(j0 + key) * DD + d);
            uint4 u;
            u.x = __float_as_uint(to_tf32(kv.x));
            u.y = __float_as_uint(to_tf32(kv.y));
            u.z = __float_as_uint(to_tf32(kv.z));
            u.w = __float_as_uint(to_tf32(kv.w));
            *(uint4*)&Kt[key * KT_LDS + d] = u;
            float4 vv = *(const float4*)(Vb + (size_t)(j0 + key) * DD + d);
            uint4 w;
            w.x = __float_as_uint(to_tf32(vv.x));
            w.y = __float_as_uint(to_tf32(vv.y));
            w.z = __float_as_uint(to_tf32(vv.z));
            w.w = __float_as_uint(to_tf32(vv.w));
            *(uint4*)&Vt[key * VT_LDS + d] = w;
        }
        __syncthreads();

        float sacc[8][4] = {};
        #pragma unroll
        for (int ks = 0; ks < 8; ks++) {
            const int kb = ks * 8 + t;
            uint32_t bf[8][2];
            #pragma unroll
            for (int nf = 0; nf < 8; nf++) {
                int n = 8 * nf + g;
                bf[nf][0] = Kt[n * KT_LDS + kb];
                bf[nf][1] = Kt[n * KT_LDS + kb + 4];
            }
            #pragma unroll
            for (int nf = 0; nf < 8; nf++)
                mma_tf32(sacc[nf], Qt[ks], bf[nf]);
        }

        if (jt == diag) {
            #pragma unroll
            for (int nf = 0; nf < 8; nf++) {
                int col = j0 + 8 * nf + 2 * t;
                if (col > r0)     sacc[nf][0] = -1e30f;
                if (col + 1 > r0) sacc[nf][1] = -1e30f;
                if (col > r0 + 8)     sacc[nf][2] = -1e30f;
                if (col + 1 > r0 + 8) sacc[nf][3] = -1e30f;
            }
        }

        #pragma unroll
        for (int hh = 0; hh < 2; hh++) {
            float tmax = -1e30f;
            #pragma unroll
            for (int nf = 0; nf < 8; nf++)
                tmax = fmaxf(tmax, fmaxf(sacc[nf][2 * hh], sacc[nf][2 * hh + 1]));
            tmax = fmaxf(tmax, __shfl_xor_sync(0xFFFFFFFF, tmax, 1));
            tmax = fmaxf(tmax, __shfl_xor_sync(0xFFFFFFFF, tmax, 2));
            float mnew = fmaxf(mrow[hh], tmax);
            float alpha = __expf(mrow[hh] - mnew);
            mrow[hh] = mnew;
            float psum = 0.f;
            #pragma unroll
            for (int nf = 0; nf < 8; nf++) {
                float p0 = __expf(sacc[nf][2 * hh] - mnew);
                float p1 = __expf(sacc[nf][2 * hh + 1] - mnew);
                sacc[nf][2 * hh] = p0;
                sacc[nf][2 * hh + 1] = p1;
                psum += p0 + p1;
            }
            psum += __shfl_xor_sync(0xFFFFFFFF, psum, 1);
            psum += __shfl_xor_sync(0xFFFFFFFF, psum, 2);
            lrow[hh] = lrow[hh] * alpha + psum;
            #pragma unroll
            for (int nf = 0; nf < 8; nf++) {
                oacc[nf][2 * hh] *= alpha;
                oacc[nf][2 * hh + 1] *= alpha;
            }
        }

        const int src0 = (lane & 28) | (t >> 1);
        const int src1 = src0 + 2;
        const int rsel = t & 1;
        #pragma unroll
        for (int ks2 = 0; ks2 < 8; ks2++) {
            uint32_t af[4];
            {
                float x0 = __shfl_sync(0xFFFFFFFF, sacc[ks2][0], src0);
                float x1 = __shfl_sync(0xFFFFFFFF, sacc[ks2][1], src0);
                af[0] = __float_as_uint(rsel ? x1 : x0);
                float y0 = __shfl_sync(0xFFFFFFFF, sacc[ks2][2], src0);
                float y1 = __shfl_sync(0xFFFFFFFF, sacc[ks2][3], src0);
                af[1] = __float_as_uint(rsel ? y1 : y0);
                float z0 = __shfl_sync(0xFFFFFFFF, sacc[ks2][0], src1);
                float z1 = __shfl_sync(0xFFFFFFFF, sacc[ks2][1], src1);
                af[2] = __float_as_uint(rsel ? z1 : z0);
                float w0 = __shfl_sync(0xFFFFFFFF, sacc[ks2][2], src1);
                float w1 = __shfl_sync(0xFFFFFFFF, sacc[ks2][3], src1);
                af[3] = __float_as_uint(rsel ? w1 : w0);
            }
            const int kb = ks2 * 8 + t;
            uint32_t bf[8][2];
            #pragma unroll
            for (int nf = 0; nf < 8; nf++) {
                int n = 8 * nf + g;
                bf[nf][0] = Vt[kb * VT_LDS + n];
                bf[nf][1] = Vt[(kb + 4) * VT_LDS + n];
            }
            #pragma unroll
            for (int nf = 0; nf < 8; nf++)
                mma_tf32(oacc[nf], af, bf[nf]);
        }
    }

    const int b = bh / HH;
    const int h = bh % HH;
    #pragma unroll
    for (int hh = 0; hh < 2; hh++) {
        float inv = 1.f / lrow[hh];
        int row = r0 + 8 * hh;
        float* yp = g_Y + ((size_t)(b * TT) + row) * CC + h * DD;
        #pragma unroll
        for (int nf = 0; nf < 8; nf++) {
            float2 v;
            v.x = to_tf32(oacc[nf][2 * hh] * inv);   // pre-round for proj
            v.y = to_tf32(oacc[nf][2 * hh + 1] * inv);
            *(float2*)(yp + 8 * nf + 2 * t) = v;
        }
    }
}

// ---------------------------------------------------------------------------
extern "C" void kernel_launch(void* const* d_in, const int* in_sizes, int n_in,
                              void* d_out, int out_size) {
    const float* x      = (const float*)d_in[0];
    const float* W_qkv  = (const float*)d_in[1];
    const float* b_qkv  = (const float*)d_in[2];
    const float* W_proj = (const float*)d_in[3];
    const float* b_proj = (const float*)d_in[4];
    float* out = (float*)d_out;

    cudaFuncSetAttribute(gemm_mma_kernel<3 * CC, 0>,
                         cudaFuncAttributeMaxDynamicSharedMemorySize, GM_SMEM_BYTES);
    cudaFuncSetAttribute(gemm_mma_kernel<CC, 1>,
                         cudaFuncAttributeMaxDynamicSharedMemorySize, GM_SMEM_BYTES);

    pre_round_kernel<<<1024, 256>>>((const float4*)x, (const float4*)W_qkv,
                                    (const float4*)W_proj);

    dim3 g1(3 * CC / GM_BN, (BB * TT) / GM_BM);   // (24, 32)
    gemm_mma_kernel<3 * CC, 0><<<g1, 256, GM_SMEM_BYTES>>>(b_qkv, nullptr);

    dim3 g2(TT / 64, BB * HH);                    // (32, 32)
    attn_mma_kernel<<<g2, 128>>>();

    dim3 g3(CC / GM_BN, (BB * TT) / GM_BM);       // (8, 32)
    gemm_mma_kernel<CC, 1><<<g3, 256, GM_SMEM_BYTES>>>(b_proj, out);
}

// round 16
// speedup vs baseline: 1.4491x; 1.0552x over previous
#include <cuda_runtime.h>
#include <cstdint>

// Problem constants
#define BB 2
#define TT 2048
#define CC 1024
#define HH 16
#define DD 64

// Scratch (allocation-free rule: __device__ globals)
__device__ float g_Q[BB * HH * TT * DD];   // [B,H,T,D], pre-rounded tf32
__device__ float g_K[BB * HH * TT * DD];   // pre-rounded tf32
__device__ float g_V[BB * HH * TT * DD];   // pre-rounded tf32
__device__ float g_Y[BB * TT * CC];        // attention output (pre-rounded tf32)
__device__ float g_X[BB * TT * CC];        // x pre-rounded to tf32
__device__ float g_Wq[CC * 3 * CC];        // W_qkv pre-rounded to tf32
__device__ float g_Wp[CC * CC];            // W_proj pre-rounded to tf32

__device__ __forceinline__ void mma_tf32(float (&c)[4], const uint32_t (&a)[4],
                                         const uint32_t (&b)[2]) {
    asm volatile(
        "mma.sync.aligned.m16n8k8.row.col.f32.tf32.tf32.f32 "
        "{%0,%1,%2,%3}, {%4,%5,%6,%7}, {%8,%9}, {%0,%1,%2,%3};"
        : "+f"(c[0]), "+f"(c[1]), "+f"(c[2]), "+f"(c[3])
        : "r"(a[0]), "r"(a[1]), "r"(a[2]), "r"(a[3]), "r"(b[0]), "r"(b[1]));
}

__device__ __forceinline__ float to_tf32(float x) {
    float r;
    asm("cvt.rna.tf32.f32 %0, %1;" : "=f"(r) : "f"(x));
    return r;
}

__device__ __forceinline__ uint32_t smem_u32(const void* p) {
    uint32_t a;
    asm("{ .reg .u64 t; cvta.to.shared.u64 t, %1; cvt.u32.u64 %0, t; }"
        : "=r"(a) : "l"(p));
    return a;
}

__device__ __forceinline__ void cp_async16(uint32_t dst, const void* src) {
    asm volatile("cp.async.cg.shared.global [%0], [%1], 16;"
                 :: "r"(dst), "l"(src));
}
#define CP_COMMIT() asm volatile("cp.async.commit_group;" ::: "memory")
#define CP_WAIT(n)  asm volatile("cp.async.wait_group %0;" :: "n"(n) : "memory")

// ---------------------------------------------------------------------------
// Pre-pass: RNA-round x / W_qkv / W_proj to tf32 once.
// ---------------------------------------------------------------------------
__global__ __launch_bounds__(256) void pre_round_kernel(
    const float4* __restrict__ x, const float4* __restrict__ wq,
    const float4* __restrict__ wp) {
    const int stride = gridDim.x * blockDim.x;
    const int i0 = blockIdx.x * blockDim.x + threadIdx.x;
    const int NX = BB * TT * CC / 4;
    const int NWQ = CC * 3 * CC / 4;
    const int NWP = CC * CC / 4;
    float4* gx = (float4*)g_X;
    float4* gq = (float4*)g_Wq;
    float4* gp = (float4*)g_Wp;
    for (int j = i0; j < NX; j += stride) {
        float4 v = x[j];
        v.x = to_tf32(v.x); v.y = to_tf32(v.y);
        v.z = to_tf32(v.z); v.w = to_tf32(v.w);
        gx[j] = v;
    }
    for (int j = i0; j < NWQ; j += stride) {
        float4 v = wq[j];
        v.x = to_tf32(v.x); v.y = to_tf32(v.y);
        v.z = to_tf32(v.z); v.w = to_tf32(v.w);
        gq[j] = v;
    }
    for (int j = i0; j < NWP; j += stride) {
        float4 v = wp[j];
        v.x = to_tf32(v.x); v.y = to_tf32(v.y);
        v.z = to_tf32(v.z); v.w = to_tf32(v.w);
        gp[j] = v;
    }
}

// ---------------------------------------------------------------------------
// tf32 mma.sync GEMM with cp.async 3-stage pipeline (R15 exact), except the
// MODE 0 epilogue now RNA-rounds Q/K/V at write time.
// ---------------------------------------------------------------------------
#define GM_BM 128
#define GM_BN 128
#define GM_BK 32
#define GM_ALD 36
#define GM_BLD 136
#define GM_NKT (CC / GM_BK)  // 32
#define GM_ASZ (GM_BM * GM_ALD)            // 4608 words
#define GM_BSZ (GM_BK * GM_BLD)            // 4352 words
#define GM_STG (GM_ASZ + GM_BSZ)           // 8960 words/stage
#define GM_SMEM_BYTES (3 * GM_STG * 4)     // 107520 B

template <int NN, int MODE>
__global__ __launch_bounds__(256, 2) void gemm_mma_kernel(
    const float* __restrict__ bias, float* __restrict__ out) {
    extern __shared__ uint32_t dsm[];

    const float* __restrict__ A = (MODE == 1) ? (const float*)g_Y : (const float*)g_X;
    const float* __restrict__ W = (MODE == 1) ? (const float*)g_Wp : (const float*)g_Wq;

    const int tid = threadIdx.x;
    const int lane = tid & 31;
    const int warp = tid >> 5;
    const int wm = warp & 1;
    const int wn = warp >> 1;
    const int g = lane >> 2;
    const int t = lane & 3;
    const int m0 = blockIdx.y * GM_BM;
    const int n0 = blockIdx.x * GM_BN;

    const uint32_t sb = smem_u32(dsm);

    auto issue = [&](int s, int kt) {
        const int k0 = kt * GM_BK;
        const uint32_t abase = sb + (s * GM_STG) * 4;
        const uint32_t bbase = sb + (s * GM_STG + GM_ASZ) * 4;
        #pragma unroll
        for (int i = 0; i < 4; i++) {
            int idx = tid + i * 256;
            int arow = idx >> 3, ac = idx & 7;
            cp_async16(abase + (arow * GM_ALD + ac * 4) * 4,
                       A + (size_t)(m0 + arow) * CC + k0 + ac * 4);
            int brow = idx >> 5, bc = idx & 31;
            cp_async16(bbase + (brow * GM_BLD + bc * 4) * 4,
                       W + (size_t)(k0 + brow) * NN + n0 + bc * 4);
        }
        CP_COMMIT();
    };

    issue(0, 0);
    issue(1, 1);

    float acc[4][4][4] = {};

    #pragma unroll 1
    for (int kt = 0; kt < GM_NKT; kt++) {
        if (kt + 1 < GM_NKT) { CP_WAIT(1); } else { CP_WAIT(0); }
        __syncthreads();

        const uint32_t* As = dsm + (kt % 3) * GM_STG;
        const uint32_t* Bs = As + GM_ASZ;

        #pragma unroll
        for (int ks = 0; ks < 4; ks++) {
            const int kb = ks * 8 + t;
            uint32_t af[4][4], bf[4][2];
            #pragma unroll
            for (int mf = 0; mf < 4; mf++) {
                int m = wm * 64 + mf * 16 + g;
                af[mf][0] = As[m * GM_ALD + kb];
                af[mf][1] = As[(m + 8) * GM_ALD + kb];
                af[mf][2] = As[m * GM_ALD + kb + 4];
                af[mf][3] = As[(m + 8) * GM_ALD + kb + 4];
            }
            #pragma unroll
            for (int nf = 0; nf < 4; nf++) {
                int n = wn * 32 + nf * 8 + g;
                bf[nf][0] = Bs[kb * GM_BLD + n];
                bf[nf][1] = Bs[(kb + 4) * GM_BLD + n];
            }
            #pragma unroll
            for (int mf = 0; mf < 4; mf++)
                #pragma unroll
                for (int nf = 0; nf < 4; nf++)
                    mma_tf32(acc[mf][nf], af[mf], bf[nf]);
        }

        if (kt + 2 < GM_NKT) issue((kt + 2) % 3, kt + 2);
    }

    #pragma unroll
    for (int mf = 0; mf < 4; mf++) {
        #pragma unroll
        for (int half = 0; half < 2; half++) {
            int row = m0 + wm * 64 + mf * 16 + g + half * 8;
            #pragma unroll
            for (int nf = 0; nf < 4; nf++) {
                int col = n0 + wn * 32 + nf * 8 + 2 * t;
                float2 v;
                v.x = acc[mf][nf][2 * half + 0] + bias[col];
                v.y = acc[mf][nf][2 * half + 1] + bias[col + 1];
                if (MODE == 0) {
                    // Round Q/K/V to tf32 once here (attention reads raw bits).
                    v.x = to_tf32(v.x);
                    v.y = to_tf32(v.y);
                    int which = col / CC;
                    int c2 = col % CC;
                    int h = c2 / DD, d = c2 % DD;
                    int b = row / TT, tt = row % TT;
                    float* base = (which == 0) ? g_Q : (which == 1) ? g_K : g_V;
                    *(float2*)(base + (((size_t)(b * HH + h) * TT + tt) * DD + d)) = v;
                } else {
                    *(float2*)(out + (size_t)row * NN + col) = v;
                }
            }
        }
    }
}

// ---------------------------------------------------------------------------
// Tensor-core flash attention: all-tf32; K/V pre-rounded so staging is pure
// cp.async (no cvt, no register round-trip).
// CTA: 128 threads / 4 warps / 64 q-rows, key tiles 64, longest-first.
// ---------------------------------------------------------------------------
#define KT_LDS 76   // uint32 stride for K (frag bank = (12g+t)%32, bijective)
#define VT_LDS 72   // uint32 stride for V (frag bank = 8t+g, bijective)

__global__ __launch_bounds__(128) void attn_mma_kernel() {
    __shared__ __align__(16) uint32_t Kt[64 * KT_LDS];   // [key][d] tf32
    __shared__ __align__(16) uint32_t Vt[64 * VT_LDS];   // [key][d] tf32

    const int bh = blockIdx.y;
    const int bx = gridDim.x - 1 - blockIdx.x;   // longest rows first
    const int qm0 = bx * 64;
    const int tid = threadIdx.x;
    const int lane = tid & 31;
    const int warp = tid >> 5;                   // 0..3
    const int g = lane >> 2;
    const int t = lane & 3;

    const float* Qb = g_Q + (size_t)bh * TT * DD;
    const float* Kb = g_K + (size_t)bh * TT * DD;
    const float* Vb = g_V + (size_t)bh * TT * DD;

    const uint32_t ktb = smem_u32(Kt);
    const uint32_t vtb = smem_u32(Vt);

    // --- Q as tf32 A-fragments (values pre-rounded; *0.125 is exact) ---
    const int r0 = qm0 + warp * 16 + g;
    const float* q0p = Qb + (size_t)r0 * DD;
    const float* q1p = q0p + 8 * DD;
    const float sc = 0.125f;
    uint32_t Qt[8][4];
    #pragma unroll
    for (int ks = 0; ks < 8; ks++) {
        int d0 = ks * 8 + t;
        Qt[ks][0] = __float_as_uint(q0p[d0] * sc);
        Qt[ks][1] = __float_as_uint(q1p[d0] * sc);
        Qt[ks][2] = __float_as_uint(q0p[d0 + 4] * sc);
        Qt[ks][3] = __float_as_uint(q1p[d0 + 4] * sc);
    }

    float oacc[8][4] = {};
    float mrow[2] = {-1e30f, -1e30f};
    float lrow[2] = {0.f, 0.f};

    const int ntiles = bx + 1;
    const int diag = bx;

    #pragma unroll 1
    for (int jt = 0; jt < ntiles; jt++) {
        const int j0 = jt * 64;
        __syncthreads();   // previous compute done before overwrite
        // --- K and V tiles via cp.async (pre-rounded tf32, raw copy) ---
        #pragma unroll
        for (int p = 0; p < 8; p++) {
            int idx = tid + p * 128;
            int key = idx >> 4;
            int d = (idx & 15) << 2;
            cp_async16(ktb + (key * KT_LDS + d) * 4,
                       Kb + (size_t)(j0 + key) * DD + d);
            cp_async16(vtb + (key * VT_LDS + d) * 4,
                       Vb + (size_t)(j0 + key) * DD + d);
        }
        CP_COMMIT();
        CP_WAIT(0);
        __syncthreads();

        // --- S = (Q*sc) . K^T  (tf32, 8 x k8) ---
        float sacc[8][4] = {};
        #pragma unroll
        for (int ks = 0; ks < 8; ks++) {
            const int kb = ks * 8 + t;
            uint32_t bf[8][2];
            #pragma unroll
            for (int nf = 0; nf < 8; nf++) {
                int n = 8 * nf + g;
                bf[nf][0] = Kt[n * KT_LDS + kb];
                bf[nf][1] = Kt[n * KT_LDS + kb + 4];
            }
            #pragma unroll
            for (int nf = 0; nf < 8; nf++)
                mma_tf32(sacc[nf], Qt[ks], bf[nf]);
        }

        // --- causal mask (diagonal tile only) ---
        if (jt == diag) {
            #pragma unroll
            for (int nf = 0; nf < 8; nf++) {
                int col = j0 + 8 * nf + 2 * t;
                if (col > r0)     sacc[nf][0] = -1e30f;
                if (col + 1 > r0) sacc[nf][1] = -1e30f;
                if (col > r0 + 8)     sacc[nf][2] = -1e30f;
                if (col + 1 > r0 + 8) sacc[nf][3] = -1e30f;
            }
        }

        // --- online softmax ---
        #pragma unroll
        for (int hh = 0; hh < 2; hh++) {
            float tmax = -1e30f;
            #pragma unroll
            for (int nf = 0; nf < 8; nf++)
                tmax = fmaxf(tmax, fmaxf(sacc[nf][2 * hh], sacc[nf][2 * hh + 1]));
            tmax = fmaxf(tmax, __shfl_xor_sync(0xFFFFFFFF, tmax, 1));
            tmax = fmaxf(tmax, __shfl_xor_sync(0xFFFFFFFF, tmax, 2));
            float mnew = fmaxf(mrow[hh], tmax);
            float alpha = __expf(mrow[hh] - mnew);
            mrow[hh] = mnew;
            float psum = 0.f;
            #pragma unroll
            for (int nf = 0; nf < 8; nf++) {
                float p0 = __expf(sacc[nf][2 * hh] - mnew);
                float p1 = __expf(sacc[nf][2 * hh + 1] - mnew);
                sacc[nf][2 * hh] = p0;
                sacc[nf][2 * hh + 1] = p1;
                psum += p0 + p1;
            }
            psum += __shfl_xor_sync(0xFFFFFFFF, psum, 1);
            psum += __shfl_xor_sync(0xFFFFFFFF, psum, 2);
            lrow[hh] = lrow[hh] * alpha + psum;
            #pragma unroll
            for (int nf = 0; nf < 8; nf++) {
                oacc[nf][2 * hh] *= alpha;
                oacc[nf][2 * hh + 1] *= alpha;
            }
        }

        // --- O += P . V  (tf32; P A-fragments gathered via shuffles) ---
        const int src0 = (lane & 28) | (t >> 1);
        const int src1 = src0 + 2;
        const int rsel = t & 1;
        #pragma unroll
        for (int ks2 = 0; ks2 < 8; ks2++) {
            uint32_t af[4];
            {
                float x0 = __shfl_sync(0xFFFFFFFF, sacc[ks2][0], src0);
                float x1 = __shfl_sync(0xFFFFFFFF, sacc[ks2][1], src0);
                af[0] = __float_as_uint(rsel ? x1 : x0);
                float y0 = __shfl_sync(0xFFFFFFFF, sacc[ks2][2], src0);
                float y1 = __shfl_sync(0xFFFFFFFF, sacc[ks2][3], src0);
                af[1] = __float_as_uint(rsel ? y1 : y0);
                float z0 = __shfl_sync(0xFFFFFFFF, sacc[ks2][0], src1);
                float z1 = __shfl_sync(0xFFFFFFFF, sacc[ks2][1], src1);
                af[2] = __float_as_uint(rsel ? z1 : z0);
                float w0 = __shfl_sync(0xFFFFFFFF, sacc[ks2][2], src1);
                float w1 = __shfl_sync(0xFFFFFFFF, sacc[ks2][3], src1);
                af[3] = __float_as_uint(rsel ? w1 : w0);
            }
            const int kb = ks2 * 8 + t;
            uint32_t bf[8][2];
            #pragma unroll
            for (int nf = 0; nf < 8; nf++) {
                int n = 8 * nf + g;
                bf[nf][0] = Vt[kb * VT_LDS + n];
                bf[nf][1] = Vt[(kb + 4) * VT_LDS + n];
            }
            #pragma unroll
            for (int nf = 0; nf < 8; nf++)
                mma_tf32(oacc[nf], af, bf[nf]);
        }
    }

    const int b = bh / HH;
    const int h = bh % HH;
    #pragma unroll
    for (int hh = 0; hh < 2; hh++) {
        float inv = 1.f / lrow[hh];
        int row = r0 + 8 * hh;
        float* yp = g_Y + ((size_t)(b * TT) + row) * CC + h * DD;
        #pragma unroll
        for (int nf = 0; nf < 8; nf++) {
            float2 v;
            v.x = to_tf32(oacc[nf][2 * hh] * inv);   // pre-round for proj
            v.y = to_tf32(oacc[nf][2 * hh + 1] * inv);
            *(float2*)(yp + 8 * nf + 2 * t) = v;
        }
    }
}

// ---------------------------------------------------------------------------
extern "C" void kernel_launch(void* const* d_in, const int* in_sizes, int n_in,
                              void* d_out, int out_size) {
    const float* x      = (const float*)d_in[0];
    const float* W_qkv  = (const float*)d_in[1];
    const float* b_qkv  = (const float*)d_in[2];
    const float* W_proj = (const float*)d_in[3];
    const float* b_proj = (const float*)d_in[4];
    float* out = (float*)d_out;

    cudaFuncSetAttribute(gemm_mma_kernel<3 * CC, 0>,
                         cudaFuncAttributeMaxDynamicSharedMemorySize, GM_SMEM_BYTES);
    cudaFuncSetAttribute(gemm_mma_kernel<CC, 1>,
                         cudaFuncAttributeMaxDynamicSharedMemorySize, GM_SMEM_BYTES);

    pre_round_kernel<<<1024, 256>>>((const float4*)x, (const float4*)W_qkv,
                                    (const float4*)W_proj);

    dim3 g1(3 * CC / GM_BN, (BB * TT) / GM_BM);   // (24, 32)
    gemm_mma_kernel<3 * CC, 0><<<g1, 256, GM_SMEM_BYTES>>>(b_qkv, nullptr);

    dim3 g2(TT / 64, BB * HH);                    // (32, 32)
    attn_mma_kernel<<<g2, 128>>>();

    dim3 g3(CC / GM_BN, (BB * TT) / GM_BM);       // (8, 32)
    gemm_mma_kernel<CC, 1><<<g3, 256, GM_SMEM_BYTES>>>(b_proj, out);
}

// round 17
// speedup vs baseline: 1.5053x; 1.0388x over previous
#include <cuda_runtime.h>
#include <cstdint>

// Problem constants
#define BB 2
#define TT 2048
#define CC 1024
#define HH 16
#define DD 64

// Scratch (allocation-free rule: __device__ globals)
__device__ float g_Q[BB * HH * TT * DD];   // [B,H,T,D], pre-rounded tf32
__device__ float g_K[BB * HH * TT * DD];   // pre-rounded tf32
__device__ float g_V[BB * HH * TT * DD];   // pre-rounded tf32
__device__ float g_Y[BB * TT * CC];        // attention output (pre-rounded tf32)
__device__ float g_X[BB * TT * CC];        // x pre-rounded to tf32
__device__ float g_Wq[CC * 3 * CC];        // W_qkv pre-rounded to tf32
__device__ float g_Wp[CC * CC];            // W_proj pre-rounded to tf32

__device__ __forceinline__ void mma_tf32(float (&c)[4], const uint32_t (&a)[4],
                                         const uint32_t (&b)[2]) {
    asm volatile(
        "mma.sync.aligned.m16n8k8.row.col.f32.tf32.tf32.f32 "
        "{%0,%1,%2,%3}, {%4,%5,%6,%7}, {%8,%9}, {%0,%1,%2,%3};"
        : "+f"(c[0]), "+f"(c[1]), "+f"(c[2]), "+f"(c[3])
        : "r"(a[0]), "r"(a[1]), "r"(a[2]), "r"(a[3]), "r"(b[0]), "r"(b[1]));
}

// Raw 32-bit fragment gather: 4x (8x8 b16) tiles == one tf32 m16k8 A-fragment
__device__ __forceinline__ void ldsm_x4(uint32_t (&r)[4], uint32_t addr) {
    asm volatile(
        "ldmatrix.sync.aligned.m8n8.x4.shared.b16 {%0,%1,%2,%3}, [%4];"
        : "=r"(r[0]), "=r"(r[1]), "=r"(r[2]), "=r"(r[3]) : "r"(addr));
}

__device__ __forceinline__ float to_tf32(float x) {
    float r;
    asm("cvt.rna.tf32.f32 %0, %1;" : "=f"(r) : "f"(x));
    return r;
}

__device__ __forceinline__ uint32_t smem_u32(const void* p) {
    uint32_t a;
    asm("{ .reg .u64 t; cvta.to.shared.u64 t, %1; cvt.u32.u64 %0, t; }"
        : "=r"(a) : "l"(p));
    return a;
}

__device__ __forceinline__ void cp_async16(uint32_t dst, const void* src) {
    asm volatile("cp.async.cg.shared.global [%0], [%1], 16;"
                 :: "r"(dst), "l"(src));
}
#define CP_COMMIT() asm volatile("cp.async.commit_group;" ::: "memory")
#define CP_WAIT(n)  asm volatile("cp.async.wait_group %0;" :: "n"(n) : "memory")

// ---------------------------------------------------------------------------
// Pre-pass: RNA-round x / W_qkv / W_proj to tf32 once.
// ---------------------------------------------------------------------------
__global__ __launch_bounds__(256) void pre_round_kernel(
    const float4* __restrict__ x, const float4* __restrict__ wq,
    const float4* __restrict__ wp) {
    const int stride = gridDim.x * blockDim.x;
    const int i0 = blockIdx.x * blockDim.x + threadIdx.x;
    const int NX = BB * TT * CC / 4;
    const int NWQ = CC * 3 * CC / 4;
    const int NWP = CC * CC / 4;
    float4* gx = (float4*)g_X;
    float4* gq = (float4*)g_Wq;
    float4* gp = (float4*)g_Wp;
    for (int j = i0; j < NX; j += stride) {
        float4 v = x[j];
        v.x = to_tf32(v.x); v.y = to_tf32(v.y);
        v.z = to_tf32(v.z); v.w = to_tf32(v.w);
        gx[j] = v;
    }
    for (int j = i0; j < NWQ; j += stride) {
        float4 v = wq[j];
        v.x = to_tf32(v.x); v.y = to_tf32(v.y);
        v.z = to_tf32(v.z); v.w = to_tf32(v.w);
        gq[j] = v;
    }
    for (int j = i0; j < NWP; j += stride) {
        float4 v = wp[j];
        v.x = to_tf32(v.x); v.y = to_tf32(v.y);
        v.z = to_tf32(v.z); v.w = to_tf32(v.w);
        gp[j] = v;
    }
}

// ---------------------------------------------------------------------------
// tf32 mma.sync GEMM, cp.async 3-stage pipeline; A-fragments via ldmatrix.x4.
// ---------------------------------------------------------------------------
#define GM_BM 128
#define GM_BN 128
#define GM_BK 32
#define GM_ALD 36
#define GM_BLD 136
#define GM_NKT (CC / GM_BK)  // 32
#define GM_ASZ (GM_BM * GM_ALD)            // 4608 words
#define GM_BSZ (GM_BK * GM_BLD)            // 4352 words
#define GM_STG (GM_ASZ + GM_BSZ)           // 8960 words/stage
#define GM_SMEM_BYTES (3 * GM_STG * 4)     // 107520 B

template <int NN, int MODE>
__global__ __launch_bounds__(256, 2) void gemm_mma_kernel(
    const float* __restrict__ bias, float* __restrict__ out) {
    extern __shared__ uint32_t dsm[];

    const float* __restrict__ A = (MODE == 1) ? (const float*)g_Y : (const float*)g_X;
    const float* __restrict__ W = (MODE == 1) ? (const float*)g_Wp : (const float*)g_Wq;

    const int tid = threadIdx.x;
    const int lane = tid & 31;
    const int warp = tid >> 5;
    const int wm = warp & 1;
    const int wn = warp >> 1;
    const int g = lane >> 2;
    const int t = lane & 3;
    const int m0 = blockIdx.y * GM_BM;
    const int n0 = blockIdx.x * GM_BN;

    const uint32_t sb = smem_u32(dsm);
    // ldmatrix per-lane offset within the A tile (bytes):
    // row = lane&15, k-offset = (lane>>4)*4 tf32
    const uint32_t lmoff = (((lane & 15) * GM_ALD + (lane >> 4) * 4)) * 4;

    auto issue = [&](int s, int kt) {
        const int k0 = kt * GM_BK;
        const uint32_t abase = sb + (s * GM_STG) * 4;
        const uint32_t bbase = sb + (s * GM_STG + GM_ASZ) * 4;
        #pragma unroll
        for (int i = 0; i < 4; i++) {
            int idx = tid + i * 256;
            int arow = idx >> 3, ac = idx & 7;
            cp_async16(abase + (arow * GM_ALD + ac * 4) * 4,
                       A + (size_t)(m0 + arow) * CC + k0 + ac * 4);
            int brow = idx >> 5, bc = idx & 31;
            cp_async16(bbase + (brow * GM_BLD + bc * 4) * 4,
                       W + (size_t)(k0 + brow) * NN + n0 + bc * 4);
        }
        CP_COMMIT();
    };

    issue(0, 0);
    issue(1, 1);

    float acc[4][4][4] = {};

    #pragma unroll 1
    for (int kt = 0; kt < GM_NKT; kt++) {
        if (kt + 1 < GM_NKT) { CP_WAIT(1); } else { CP_WAIT(0); }
        __syncthreads();

        const uint32_t abase = sb + ((kt % 3) * GM_STG) * 4;
        const uint32_t* Bs = dsm + (kt % 3) * GM_STG + GM_ASZ;

        #pragma unroll
        for (int ks = 0; ks < 4; ks++) {
            const int kb = ks * 8 + t;
            uint32_t af[4][4], bf[4][2];
            #pragma unroll
            for (int mf = 0; mf < 4; mf++) {
                ldsm_x4(af[mf], abase + lmoff +
                        (((wm * 64 + mf * 16) * GM_ALD + ks * 8)) * 4);
            }
            #pragma unroll
            for (int nf = 0; nf < 4; nf++) {
                int n = wn * 32 + nf * 8 + g;
                bf[nf][0] = Bs[kb * GM_BLD + n];
                bf[nf][1] = Bs[(kb + 4) * GM_BLD + n];
            }
            #pragma unroll
            for (int mf = 0; mf < 4; mf++)
                #pragma unroll
                for (int nf = 0; nf < 4; nf++)
                    mma_tf32(acc[mf][nf], af[mf], bf[nf]);
        }

        if (kt + 2 < GM_NKT) issue((kt + 2) % 3, kt + 2);
    }

    #pragma unroll
    for (int mf = 0; mf < 4; mf++) {
        #pragma unroll
        for (int half = 0; half < 2; half++) {
            int row = m0 + wm * 64 + mf * 16 + g + half * 8;
            #pragma unroll
            for (int nf = 0; nf < 4; nf++) {
                int col = n0 + wn * 32 + nf * 8 + 2 * t;
                float2 v;
                v.x = acc[mf][nf][2 * half + 0] + bias[col];
                v.y = acc[mf][nf][2 * half + 1] + bias[col + 1];
                if (MODE == 0) {
                    v.x = to_tf32(v.x);
                    v.y = to_tf32(v.y);
                    int which = col / CC;
                    int c2 = col % CC;
                    int h = c2 / DD, d = c2 % DD;
                    int b = row / TT, tt = row % TT;
                    float* base = (which == 0) ? g_Q : (which == 1) ? g_K : g_V;
                    *(float2*)(base + (((size_t)(b * HH + h) * TT + tt) * DD + d)) = v;
                } else {
                    *(float2*)(out + (size_t)row * NN + col) = v;
                }
            }
        }
    }
}

// ---------------------------------------------------------------------------
// Tensor-core flash attention: all-tf32; cp.async K/V staging; S-phase K
// fragments via ldmatrix.x4.
// CTA: 128 threads / 4 warps / 64 q-rows, key tiles 64, longest-first.
// ---------------------------------------------------------------------------
#define KT_LDS 76   // uint32 stride for K
#define VT_LDS 72   // uint32 stride for V (frag bank = 8t+g, bijective)

__global__ __launch_bounds__(128) void attn_mma_kernel() {
    __shared__ __align__(16) uint32_t Kt[64 * KT_LDS];   // [key][d] tf32
    __shared__ __align__(16) uint32_t Vt[64 * VT_LDS];   // [key][d] tf32

    const int bh = blockIdx.y;
    const int bx = gridDim.x - 1 - blockIdx.x;   // longest rows first
    const int qm0 = bx * 64;
    const int tid = threadIdx.x;
    const int lane = tid & 31;
    const int warp = tid >> 5;                   // 0..3
    const int g = lane >> 2;
    const int t = lane & 3;

    const float* Qb = g_Q + (size_t)bh * TT * DD;
    const float* Kb = g_K + (size_t)bh * TT * DD;
    const float* Vb = g_V + (size_t)bh * TT * DD;

    const uint32_t ktb = smem_u32(Kt);
    const uint32_t vtb = smem_u32(Vt);
    // ldmatrix lane offset for K B-frag pairs:
    // tiles: (nf0,lo),(nf0,hi),(nf0+1,lo),(nf0+1,hi)
    // row = (lane&7) + ((lane>>4)&1)*8, k-offset = ((lane>>3)&1)*4
    const uint32_t klmoff =
        ((((lane & 7) + ((lane >> 4) & 1) * 8) * KT_LDS +
          ((lane >> 3) & 1) * 4)) * 4;

    // --- Q as tf32 A-fragments (values pre-rounded; *0.125 is exact) ---
    const int r0 = qm0 + warp * 16 + g;
    const float* q0p = Qb + (size_t)r0 * DD;
    const float* q1p = q0p + 8 * DD;
    const float sc = 0.125f;
    uint32_t Qt[8][4];
    #pragma unroll
    for (int ks = 0; ks < 8; ks++) {
        int d0 = ks * 8 + t;
        Qt[ks][0] = __float_as_uint(q0p[d0] * sc);
        Qt[ks][1] = __float_as_uint(q1p[d0] * sc);
        Qt[ks][2] = __float_as_uint(q0p[d0 + 4] * sc);
        Qt[ks][3] = __float_as_uint(q1p[d0 + 4] * sc);
    }

    float oacc[8][4] = {};
    float mrow[2] = {-1e30f, -1e30f};
    float lrow[2] = {0.f, 0.f};

    const int ntiles = bx + 1;
    const int diag = bx;

    #pragma unroll 1
    for (int jt = 0; jt < ntiles; jt++) {
        const int j0 = jt * 64;
        __syncthreads();
        #pragma unroll
        for (int p = 0; p < 8; p++) {
            int idx = tid + p * 128;
            int key = idx >> 4;
            int d = (idx & 15) << 2;
            cp_async16(ktb + (key * KT_LDS + d) * 4,
                       Kb + (size_t)(j0 + key) * DD + d);
            cp_async16(vtb + (key * VT_LDS + d) * 4,
                       Vb + (size_t)(j0 + key) * DD + d);
        }
        CP_COMMIT();
        CP_WAIT(0);
        __syncthreads();

        // --- S = (Q*sc) . K^T  (tf32; K frags via ldmatrix pairs) ---
        float sacc[8][4] = {};
        #pragma unroll
        for (int ks = 0; ks < 8; ks++) {
            uint32_t bf[4][4];   // [pair][(nf0:0,1), (nf0+1:2,3)]
            #pragma unroll
            for (int pr = 0; pr < 4; pr++) {
                ldsm_x4(bf[pr], ktb + klmoff +
                        (((pr * 16) * KT_LDS + ks * 8)) * 4);
            }
            #pragma unroll
            for (int pr = 0; pr < 4; pr++) {
                uint32_t b0[2] = {bf[pr][0], bf[pr][1]};
                uint32_t b1[2] = {bf[pr][2], bf[pr][3]};
                mma_tf32(sacc[2 * pr], Qt[ks], b0);
                mma_tf32(sacc[2 * pr + 1], Qt[ks], b1);
            }
        }

        // --- causal mask (diagonal tile only) ---
        if (jt == diag) {
            #pragma unroll
            for (int nf = 0; nf < 8; nf++) {
                int col = j0 + 8 * nf + 2 * t;
                if (col > r0)     sacc[nf][0] = -1e30f;
                if (col + 1 > r0) sacc[nf][1] = -1e30f;
                if (col > r0 + 8)     sacc[nf][2] = -1e30f;
                if (col + 1 > r0 + 8) sacc[nf][3] = -1e30f;
            }
        }

        // --- online softmax ---
        #pragma unroll
        for (int hh = 0; hh < 2; hh++) {
            float tmax = -1e30f;
            #pragma unroll
            for (int nf = 0; nf < 8; nf++)
                tmax = fmaxf(tmax, fmaxf(sacc[nf][2 * hh], sacc[nf][2 * hh + 1]));
            tmax = fmaxf(tmax, __shfl_xor_sync(0xFFFFFFFF, tmax, 1));
            tmax = fmaxf(tmax, __shfl_xor_sync(0xFFFFFFFF, tmax, 2));
            float mnew = fmaxf(mrow[hh], tmax);
            float alpha = __expf(mrow[hh] - mnew);
            mrow[hh] = mnew;
            float psum = 0.f;
            #pragma unroll
            for (int nf = 0; nf < 8; nf++) {
                float p0 = __expf(sacc[nf][2 * hh] - mnew);
                float p1 = __expf(sacc[nf][2 * hh + 1] - mnew);
                sacc[nf][2 * hh] = p0;
                sacc[nf][2 * hh + 1] = p1;
                psum += p0 + p1;
            }
            psum += __shfl_xor_sync(0xFFFFFFFF, psum, 1);
            psum += __shfl_xor_sync(0xFFFFFFFF, psum, 2);
            lrow[hh] = lrow[hh] * alpha + psum;
            #pragma unroll
            for (int nf = 0; nf < 8; nf++) {
                oacc[nf][2 * hh] *= alpha;
                oacc[nf][2 * hh + 1] *= alpha;
            }
        }

        // --- O += P . V  (tf32; P A-fragments gathered via shuffles) ---
        const int src0 = (lane & 28) | (t >> 1);
        const int src1 = src0 + 2;
        const int rsel = t & 1;
        #pragma unroll
        for (int ks2 = 0; ks2 < 8; ks2++) {
            uint32_t af[4];
            {
                float x0 = __shfl_sync(0xFFFFFFFF, sacc[ks2][0], src0);
                float x1 = __shfl_sync(0xFFFFFFFF, sacc[ks2][1], src0);
                af[0] = __float_as_uint(rsel ? x1 : x0);
                float y0 = __shfl_sync(0xFFFFFFFF, sacc[ks2][2], src0);
                float y1 = __shfl_sync(0xFFFFFFFF, sacc[ks2][3], src0);
                af[1] = __float_as_uint(rsel ? y1 : y0);
                float z0 = __shfl_sync(0xFFFFFFFF, sacc[ks2][0], src1);
                float z1 = __shfl_sync(0xFFFFFFFF, sacc[ks2][1], src1);
                af[2] = __float_as_uint(rsel ? z1 : z0);
                float w0 = __shfl_sync(0xFFFFFFFF, sacc[ks2][2], src1);
                float w1 = __shfl_sync(0xFFFFFFFF, sacc[ks2][3], src1);
                af[3] = __float_as_uint(rsel ? w1 : w0);
            }
            const int kb = ks2 * 8 + t;
            uint32_t bf[8][2];
            #pragma unroll
            for (int nf = 0; nf < 8; nf++) {
                int n = 8 * nf + g;
                bf[nf][0] = Vt[kb * VT_LDS + n];
                bf[nf][1] = Vt[(kb + 4) * VT_LDS + n];
            }
            #pragma unroll
            for (int nf = 0; nf < 8; nf++)
                mma_tf32(oacc[nf], af, bf[nf]);
        }
    }

    const int b = bh / HH;
    const int h = bh % HH;
    #pragma unroll
    for (int hh = 0; hh < 2; hh++) {
        float inv = 1.f / lrow[hh];
        int row = r0 + 8 * hh;
        float* yp = g_Y + ((size_t)(b * TT) + row) * CC + h * DD;
        #pragma unroll
        for (int nf = 0; nf < 8; nf++) {
            float2 v;
            v.x = to_tf32(oacc[nf][2 * hh] * inv);   // pre-round for proj
            v.y = to_tf32(oacc[nf][2 * hh + 1] * inv);
            *(float2*)(yp + 8 * nf + 2 * t) = v;
        }
    }
}

// ---------------------------------------------------------------------------
extern "C" void kernel_launch(void* const* d_in, const int* in_sizes, int n_in,
                              void* d_out, int out_size) {
    const float* x      = (const float*)d_in[0];
    const float* W_qkv  = (const float*)d_in[1];
    const float* b_qkv  = (const float*)d_in[2];
    const float* W_proj = (const float*)d_in[3];
    const float* b_proj = (const float*)d_in[4];
    float* out = (float*)d_out;

    cudaFuncSetAttribute(gemm_mma_kernel<3 * CC, 0>,
                         cudaFuncAttributeMaxDynamicSharedMemorySize, GM_SMEM_BYTES);
    cudaFuncSetAttribute(gemm_mma_kernel<CC, 1>,
                         cudaFuncAttributeMaxDynamicSharedMemorySize, GM_SMEM_BYTES);

    pre_round_kernel<<<1024, 256>>>((const float4*)x, (const float4*)W_qkv,
                                    (const float4*)W_proj);

    dim3 g1(3 * CC / GM_BN, (BB * TT) / GM_BM);   // (24, 32)
    gemm_mma_kernel<3 * CC, 0><<<g1, 256, GM_SMEM_BYTES>>>(b_qkv, nullptr);

    dim3 g2(TT / 64, BB * HH);                    // (32, 32)
    attn_mma_kernel<<<g2, 128>>>();

    dim3 g3(CC / GM_BN, (BB * TT) / GM_BM);       // (8, 32)
    gemm_mma_kernel<CC, 1><<<g3, 256, GM_SMEM_BYTES>>>(b_proj, out);
}